// round 8
// baseline (speedup 1.0000x reference)
#include <cuda_runtime.h>
#include <cuda_bf16.h>
#include <math.h>
#include <stdint.h>

typedef unsigned int u32;
typedef unsigned short u16;

#define Bc   4
#define NQc  2048
#define NKc  2048
#define Dc   1024
#define Hc   8
#define DKc  128
#define DVc  128
#define DOc  1024
#define HBc  32
#define KTILES 16

// fp32 scratch
__device__ float g_outh[(size_t)Bc*NQc*Hc*DVc];
__device__ float g_tM  [(size_t)HBc*KTILES*2*NQc];
__device__ float g_tL  [(size_t)HBc*KTILES*2*NQc];
__device__ float g_rowM[(size_t)HBc*NQc];
__device__ float g_rowLi[(size_t)HBc*NQc];
// bf16 hi/lo planes
__device__ u16 g_qh_hi[(size_t)Bc*NQc*Hc*DKc];
__device__ u16 g_qh_lo[(size_t)Bc*NQc*Hc*DKc];
__device__ u16 g_kh_hi[(size_t)Bc*NKc*DKc];
__device__ u16 g_kh_lo[(size_t)Bc*NKc*DKc];
__device__ u16 g_vh_hi[(size_t)Bc*NKc*DVc];
__device__ u16 g_vh_lo[(size_t)Bc*NKc*DVc];
__device__ u16 g_vT_hi[(size_t)Bc*DVc*NKc];
__device__ u16 g_vT_lo[(size_t)Bc*DVc*NKc];

// ---------------- helpers ---------------------------------------------------
__device__ __forceinline__ u32 s2u(const void* p){
    u32 a; asm("{ .reg .u64 t; cvta.to.shared.u64 t, %1; cvt.u32.u64 %0, t; }"
               : "=r"(a) : "l"(p)); return a;
}
__device__ __forceinline__ u32 pkbf2(float a, float b){
    u32 ra = (u32)__bfloat16_as_ushort(__float2bfloat16(a));
    u32 rb = (u32)__bfloat16_as_ushort(__float2bfloat16(b));
    return ra | (rb << 16);
}
__device__ __forceinline__ float bres(float x){
    return x - __bfloat162float(__float2bfloat16(x));
}
__device__ __forceinline__ void ldmx4(u32* r, u32 addr){
    asm volatile("ldmatrix.sync.aligned.m8n8.x4.shared.b16 {%0,%1,%2,%3}, [%4];"
        : "=r"(r[0]), "=r"(r[1]), "=r"(r[2]), "=r"(r[3]) : "r"(addr));
}
__device__ __forceinline__ void mma16816(float* c, const u32* a, u32 b0, u32 b1){
    asm volatile("mma.sync.aligned.m16n8k16.row.col.f32.bf16.bf16.f32 "
        "{%0,%1,%2,%3}, {%4,%5,%6,%7}, {%8,%9}, {%0,%1,%2,%3};"
        : "+f"(c[0]), "+f"(c[1]), "+f"(c[2]), "+f"(c[3])
        : "r"(a[0]), "r"(a[1]), "r"(a[2]), "r"(a[3]), "r"(b0), "r"(b1));
}

// ---- fp32 -> bf16 hi/lo convert path (projection inputs only) ---------------
template<int COLS>
__device__ __forceinline__ void loadregs(const float* __restrict__ g, int ldA,
                                         float4* pre, int tid){
    const int PER = (128*COLS/4)/256;
#pragma unroll
    for (int i = 0; i < PER; i++){
        int idx = tid + i*256;
        int row = idx / (COLS/4);
        int c4  = (idx % (COLS/4))*4;
        pre[i] = *(const float4*)(g + (size_t)row*ldA + c4);
    }
}
template<int COLS, int STRIDE>
__device__ __forceinline__ void convert(const float4* pre, char* smHi, char* smLo, int tid){
    const int PER = (128*COLS/4)/256;
#pragma unroll
    for (int i = 0; i < PER; i++){
        int idx = tid + i*256;
        int row = idx / (COLS/4);
        int c4  = (idx % (COLS/4))*4;
        float4 v = pre[i];
        int off = (row*STRIDE + c4)*2;
        *(uint2*)(smHi+off) = make_uint2(pkbf2(v.x,v.y), pkbf2(v.z,v.w));
        *(uint2*)(smLo+off) = make_uint2(pkbf2(bres(v.x),bres(v.y)),
                                         pkbf2(bres(v.z),bres(v.w)));
    }
}

// ---- bf16-plane copy path (no conversion): 128 rows x 128 cols --------------
template<int STRIDE>
__device__ __forceinline__ void ldcopy128(const u16* __restrict__ g, int ldA,
                                          char* smd, int tid){
#pragma unroll
    for (int i = 0; i < 8; i++){
        int idx = tid + i*256;
        int row = idx >> 4;
        int c8  = (idx & 15) << 3;
        uint4 v = *(const uint4*)(g + (size_t)row*ldA + c8);
        *(uint4*)(smd + (row*STRIDE + c8)*2) = v;
    }
}
__device__ __forceinline__ void loadregs16(const u16* __restrict__ g, int ldA,
                                           uint4* pre, int tid){
#pragma unroll
    for (int i = 0; i < 8; i++){
        int idx = tid + i*256;
        int row = idx >> 4;
        int c8  = (idx & 15) << 3;
        pre[i] = *(const uint4*)(g + (size_t)row*ldA + c8);
    }
}
template<int STRIDE>
__device__ __forceinline__ void storeregs16(const uint4* pre, char* smd, int tid){
#pragma unroll
    for (int i = 0; i < 8; i++){
        int idx = tid + i*256;
        int row = idx >> 4;
        int c8  = (idx & 15) << 3;
        *(uint4*)(smd + (row*STRIDE + c8)*2) = pre[i];
    }
}

// One k-step (k=16): warp computes 32x64 using split bf16x3.
template<int SA, int SB>
__device__ __forceinline__ void wstep(u32 Ah, u32 Al, u32 Bh, u32 Bl,
                                      int ks, int warp_m, int warp_n, int lane,
                                      float c[2][8][4]){
    const int rsel = lane & 15, ksel = (lane >> 4) << 3;
    const int kb = ks*16 + ksel;
    u32 ah[2][4], al[2][4], bh[4][4], bl[4][4];
#pragma unroll
    for (int mt = 0; mt < 2; mt++){
        u32 off = (u32)((warp_m*32 + mt*16 + rsel)*SA + kb)*2;
        ldmx4(ah[mt], Ah + off);
        ldmx4(al[mt], Al + off);
    }
#pragma unroll
    for (int p = 0; p < 4; p++){
        u32 off = (u32)((warp_n*64 + p*16 + rsel)*SB + kb)*2;
        ldmx4(bh[p], Bh + off);
        ldmx4(bl[p], Bl + off);
    }
#pragma unroll
    for (int mt = 0; mt < 2; mt++)
#pragma unroll
        for (int nt = 0; nt < 8; nt++){
            int p = nt >> 1, s = nt & 1;
            u32 b0h = bh[p][s], b1h = bh[p][2+s];
            u32 b0l = bl[p][s], b1l = bl[p][2+s];
            mma16816(c[mt][nt], ah[mt], b0h, b1h);
            mma16816(c[mt][nt], ah[mt], b0l, b1l);
            mma16816(c[mt][nt], al[mt], b0h, b1h);
        }
}

// ---------------------------------------------------------------------------
// proj: C = A[M,K] @ W[N,K]^T + bias. PLANES=1 -> write bf16 hi/lo planes,
// PLANES=0 -> write fp32.
// ---------------------------------------------------------------------------
#define PSTR 72
#define PTILE (128*PSTR*2)
template<int PLANES>
__global__ void __launch_bounds__(256) proj_mma(
    const float* __restrict__ A, const float* __restrict__ W,
    const float* __restrict__ bias, float* __restrict__ Cf,
    u16* __restrict__ Chi, u16* __restrict__ Clo,
    int M, int N, int K)
{
    extern __shared__ char sm[];
    u32 sb = s2u(sm);
    const int tid = threadIdx.x, lane = tid & 31, wid = tid >> 5;
    const int warp_m = wid & 3, warp_n = wid >> 2;
    const int n0 = blockIdx.x << 7, m0 = blockIdx.y << 7;

    char* Ahp = sm;            char* Alp = sm + PTILE;
    char* Bhp = sm + 2*PTILE;  char* Blp = sm + 3*PTILE;
    const u32 Ah = sb, Al = sb + PTILE, Bh = sb + 2*PTILE, Bl = sb + 3*PTILE;

    float c[2][8][4];
#pragma unroll
    for (int i=0;i<2;i++) for (int j=0;j<8;j++) for (int q=0;q<4;q++) c[i][j][q]=0.f;

    float4 preA[8], preW[8];
    loadregs<64>(A + (size_t)m0*K, K, preA, tid);
    loadregs<64>(W + (size_t)n0*K, K, preW, tid);

    const int NC = K/64;
    for (int kc = 0; kc < NC; kc++){
        convert<64,PSTR>(preA, Ahp, Alp, tid);
        convert<64,PSTR>(preW, Bhp, Blp, tid);
        __syncthreads();
        if (kc + 1 < NC){
            loadregs<64>(A + (size_t)m0*K + (kc+1)*64, K, preA, tid);
            loadregs<64>(W + (size_t)n0*K + (kc+1)*64, K, preW, tid);
        }
#pragma unroll
        for (int ks = 0; ks < 4; ks++)
            wstep<PSTR,PSTR>(Ah, Al, Bh, Bl, ks, warp_m, warp_n, lane, c);
        __syncthreads();
    }

#pragma unroll
    for (int mt = 0; mt < 2; mt++)
#pragma unroll
        for (int rh = 0; rh < 2; rh++){
            int row = m0 + warp_m*32 + mt*16 + rh*8 + (lane >> 2);
#pragma unroll
            for (int nt = 0; nt < 8; nt++){
                int col = n0 + warp_n*64 + nt*8 + ((lane & 3) << 1);
                float ox = c[mt][nt][rh*2+0] + __ldg(bias + col);
                float oy = c[mt][nt][rh*2+1] + __ldg(bias + col + 1);
                if (PLANES){
                    *(u32*)(Chi + (size_t)row*N + col) = pkbf2(ox, oy);
                    *(u32*)(Clo + (size_t)row*N + col) = pkbf2(bres(ox), bres(oy));
                } else {
                    *(float2*)(Cf + (size_t)row*N + col) = make_float2(ox, oy);
                }
            }
        }
}

// ---------------------------------------------------------------------------
// scores: Q,K from bf16 planes (pure copies). Raw S -> attn; stats -> tM/tL.
// ---------------------------------------------------------------------------
#define SSTR 136
#define STILE (128*SSTR*2)
__global__ void __launch_bounds__(256) scores_mma(
    const u16* __restrict__ qh_hi, const u16* __restrict__ qh_lo,
    const u16* __restrict__ kh_hi, const u16* __restrict__ kh_lo,
    const float* __restrict__ mask, float* __restrict__ attn,
    float* __restrict__ tM, float* __restrict__ tL)
{
    extern __shared__ char sm[];
    u32 sb = s2u(sm);
    const int tid = threadIdx.x, lane = tid & 31, wid = tid >> 5;
    const int warp_m = wid & 3, warp_n = wid >> 2;
    const int q0 = blockIdx.x << 7;
    const int hb = blockIdx.y, b = hb >> 3, h = hb & 7;

    char* Qhp = sm;            char* Qlp = sm + STILE;
    char* Khp = sm + 2*STILE;  char* Klp = sm + 3*STILE;
    const u32 Qh = sb, Ql = sb + STILE, Kh = sb + 2*STILE, Kl = sb + 3*STILE;

    const size_t qoff = (size_t)(b*NQc + q0)*Dc + h*DKc;
    ldcopy128<SSTR>(qh_hi + qoff, Dc, Qhp, tid);
    ldcopy128<SSTR>(qh_lo + qoff, Dc, Qlp, tid);

    const u16* kbh = kh_hi + (size_t)b*NKc*DKc;
    const u16* kbl = kh_lo + (size_t)b*NKc*DKc;
    uint4 preH[8], preL[8];
    loadregs16(kbh, DKc, preH, tid);
    loadregs16(kbl, DKc, preL, tid);

    const float scale = 0.08838834764831845f;

    for (int kt = 0; kt < KTILES; kt++){
        storeregs16<SSTR>(preH, Khp, tid);
        storeregs16<SSTR>(preL, Klp, tid);
        __syncthreads();
        if (kt + 1 < KTILES){
            loadregs16(kbh + (size_t)((kt+1)*128)*DKc, DKc, preH, tid);
            loadregs16(kbl + (size_t)((kt+1)*128)*DKc, DKc, preL, tid);
        }

        float c[2][8][4];
#pragma unroll
        for (int i=0;i<2;i++) for (int j=0;j<8;j++) for (int q=0;q<4;q++) c[i][j][q]=0.f;
#pragma unroll
        for (int ks = 0; ks < 8; ks++)
            wstep<SSTR,SSTR>(Qh, Ql, Kh, Kl, ks, warp_m, warp_n, lane, c);

#pragma unroll
        for (int mt = 0; mt < 2; mt++)
#pragma unroll
            for (int rh = 0; rh < 2; rh++){
                int row = q0 + warp_m*32 + mt*16 + rh*8 + (lane >> 2);
                const float* mrow = mask + ((size_t)b*NQc + row)*NKc + kt*128;
                float* arow = attn + ((size_t)(h*Bc + b)*NQc + row)*NKc + kt*128;
                float mx = -1e30f, le = 0.f;
#pragma unroll
                for (int nt = 0; nt < 8; nt++){
                    int col = warp_n*64 + nt*8 + ((lane & 3) << 1);
                    float2 mv = *(const float2*)(mrow + col);
                    float s0 = fmaf(c[mt][nt][rh*2+0], scale, mv.x);
                    float s1 = fmaf(c[mt][nt][rh*2+1], scale, mv.y);
                    *(float2*)(arow + col) = make_float2(s0, s1);
                    float m2 = fmaxf(s0, s1);
                    float nm = fmaxf(mx, m2);
                    le = le*__expf(mx - nm) + __expf(s0 - nm) + __expf(s1 - nm);
                    mx = nm;
                }
#pragma unroll
                for (int off = 1; off <= 2; off <<= 1){
                    float mo = __shfl_xor_sync(0xFFFFFFFFu, mx, off);
                    float lo = __shfl_xor_sync(0xFFFFFFFFu, le, off);
                    float nm = fmaxf(mx, mo);
                    le = le*__expf(mx - nm) + lo*__expf(mo - nm);
                    mx = nm;
                }
                if ((lane & 3) == 0){
                    size_t o = ((size_t)hb*KTILES*2 + kt*2 + warp_n)*NQc + row;
                    tM[o] = mx; tL[o] = le;
                }
            }
        __syncthreads();
    }
}

// per-row combine over 32 slots
__global__ void reduce_rows(const float* __restrict__ tM, const float* __restrict__ tL,
                            float* __restrict__ rowM, float* __restrict__ rowLi)
{
    int idx = blockIdx.x * blockDim.x + threadIdx.x;
    if (idx >= HBc*NQc) return;
    int bz = idx / NQc, row = idx % NQc;
    float M = -1e30f;
#pragma unroll
    for (int t = 0; t < KTILES*2; t++)
        M = fmaxf(M, tM[(size_t)(bz*KTILES*2 + t)*NQc + row]);
    float L = 0.f;
#pragma unroll
    for (int t = 0; t < KTILES*2; t++)
        L += tL[(size_t)(bz*KTILES*2 + t)*NQc + row]
           * __expf(tM[(size_t)(bz*KTILES*2 + t)*NQc + row] - M);
    rowM[idx] = M; rowLi[idx] = 1.0f / L;
}

// bf16 planes [b,k,d] -> [b,d,k]
__global__ void transpose_v(const u16* __restrict__ vh_hi, const u16* __restrict__ vh_lo,
                            u16* __restrict__ vT_hi, u16* __restrict__ vT_lo){
    __shared__ u16 th[32][34], tl[32][34];
    int b = blockIdx.z;
    int k0 = blockIdx.x*32, d0 = blockIdx.y*32;
    int x = threadIdx.x, y = threadIdx.y;
#pragma unroll
    for (int i = 0; i < 32; i += 8){
        size_t gi = (size_t)(b*NKc + k0 + y + i)*DVc + d0 + x;
        th[y+i][x] = vh_hi[gi];
        tl[y+i][x] = vh_lo[gi];
    }
    __syncthreads();
#pragma unroll
    for (int i = 0; i < 32; i += 8){
        size_t go = ((size_t)b*DVc + d0 + y + i)*NKc + k0 + x;
        vT_hi[go] = th[x][y+i];
        vT_lo[go] = tl[x][y+i];
    }
}

// ---------------------------------------------------------------------------
// attv: normalize P (write back), outh = P @ V via vT planes.
// ---------------------------------------------------------------------------
__global__ void __launch_bounds__(256) attv_mma(
    const u16* __restrict__ vT_hi, const u16* __restrict__ vT_lo,
    float* __restrict__ attn,
    const float* __restrict__ rowM, const float* __restrict__ rowLi,
    float* __restrict__ outh)
{
    extern __shared__ char sm[];
    __shared__ float Ms[128], Li[128];
    u32 sb = s2u(sm);
    const int tid = threadIdx.x, lane = tid & 31, wid = tid >> 5;
    const int warp_m = wid & 3, warp_n = wid >> 2;
    const int q0 = blockIdx.x << 7;
    const int hb = blockIdx.y, b = hb >> 3, h = hb & 7;

    char* Php = sm;            char* Plp = sm + STILE;
    char* Vhp = sm + 2*STILE;  char* Vlp = sm + 3*STILE;
    const u32 Ph = sb, Pl = sb + STILE, Vh = sb + 2*STILE, Vl = sb + 3*STILE;

    if (tid < 128){
        int gi = hb*NQc + q0 + tid;
        Ms[tid] = rowM[gi];
        Li[tid] = rowLi[gi];
    }

    float* abase = attn + ((size_t)(h*Bc + b)*NQc + q0)*NKc;
    const u16* vbh = vT_hi + (size_t)b*DVc*NKc;
    const u16* vbl = vT_lo + (size_t)b*DVc*NKc;

    float4 preP[16];
    loadregs<128>(abase, NKc, preP, tid);
    __syncthreads();

    float c[2][8][4];
#pragma unroll
    for (int i=0;i<2;i++) for (int j=0;j<8;j++) for (int q=0;q<4;q++) c[i][j][q]=0.f;

    for (int kt = 0; kt < KTILES; kt++){
        // normalize prefetched P chunk, write back, stage bf16 hi/lo
#pragma unroll
        for (int i = 0; i < 16; i++){
            int idx = tid + i*256;
            int row = idx >> 5, c4 = (idx & 31) << 2;
            float4 s = preP[i];
            float mm = Ms[row], li = Li[row];
            float4 p;
            p.x = __expf(s.x - mm)*li; p.y = __expf(s.y - mm)*li;
            p.z = __expf(s.z - mm)*li; p.w = __expf(s.w - mm)*li;
            *(float4*)(abase + (size_t)row*NKc + kt*128 + c4) = p;
            int off = (row*SSTR + c4)*2;
            *(uint2*)(Php+off) = make_uint2(pkbf2(p.x,p.y), pkbf2(p.z,p.w));
            *(uint2*)(Plp+off) = make_uint2(pkbf2(bres(p.x),bres(p.y)),
                                            pkbf2(bres(p.z),bres(p.w)));
        }
        ldcopy128<SSTR>(vbh + kt*128, NKc, Vhp, tid);
        ldcopy128<SSTR>(vbl + kt*128, NKc, Vlp, tid);
        __syncthreads();
        if (kt + 1 < KTILES)
            loadregs<128>(abase + (kt+1)*128, NKc, preP, tid);
#pragma unroll
        for (int ks = 0; ks < 8; ks++)
            wstep<SSTR,SSTR>(Ph, Pl, Vh, Vl, ks, warp_m, warp_n, lane, c);
        __syncthreads();
    }

#pragma unroll
    for (int mt = 0; mt < 2; mt++)
#pragma unroll
        for (int rh = 0; rh < 2; rh++){
            int row = q0 + warp_m*32 + mt*16 + rh*8 + (lane >> 2);
            float* op = outh + (size_t)(b*NQc + row)*(Hc*DVc) + h*DVc;
#pragma unroll
            for (int nt = 0; nt < 8; nt++){
                int col = warp_n*64 + nt*8 + ((lane & 3) << 1);
                *(float2*)(op + col) = make_float2(c[mt][nt][rh*2+0], c[mt][nt][rh*2+1]);
            }
        }
}

// ---------------------------------------------------------------------------
extern "C" void kernel_launch(void* const* d_in, const int* in_sizes, int n_in,
                              void* d_out, int out_size)
{
    const float* q    = (const float*)d_in[0];
    const float* k    = (const float*)d_in[1];
    const float* v    = (const float*)d_in[2];
    const float* mask = (const float*)d_in[3];
    const float* Wq   = (const float*)d_in[4];
    const float* bq   = (const float*)d_in[5];
    const float* Wk   = (const float*)d_in[6];
    const float* bk   = (const float*)d_in[7];
    const float* Wv   = (const float*)d_in[8];
    const float* bv   = (const float*)d_in[9];
    const float* Wo   = (const float*)d_in[10];
    const float* bo   = (const float*)d_in[11];

    float* attn = (float*)d_out;
    float* outp = attn + (size_t)HBc*NQc*NKc;

    float *outh,*tM,*tL,*rm,*rli;
    u16 *qhh,*qhl,*khh,*khl,*vhh,*vhl,*vth,*vtl;
    cudaGetSymbolAddress((void**)&outh, g_outh);
    cudaGetSymbolAddress((void**)&tM,   g_tM);
    cudaGetSymbolAddress((void**)&tL,   g_tL);
    cudaGetSymbolAddress((void**)&rm,   g_rowM);
    cudaGetSymbolAddress((void**)&rli,  g_rowLi);
    cudaGetSymbolAddress((void**)&qhh,  g_qh_hi);
    cudaGetSymbolAddress((void**)&qhl,  g_qh_lo);
    cudaGetSymbolAddress((void**)&khh,  g_kh_hi);
    cudaGetSymbolAddress((void**)&khl,  g_kh_lo);
    cudaGetSymbolAddress((void**)&vhh,  g_vh_hi);
    cudaGetSymbolAddress((void**)&vhl,  g_vh_lo);
    cudaGetSymbolAddress((void**)&vth,  g_vT_hi);
    cudaGetSymbolAddress((void**)&vtl,  g_vT_lo);

    const int PROJ_SM = 4*PTILE;           // 73728
    const int BIG_SM  = 4*STILE;           // 139264
    cudaFuncSetAttribute(proj_mma<1>, cudaFuncAttributeMaxDynamicSharedMemorySize, PROJ_SM);
    cudaFuncSetAttribute(proj_mma<0>, cudaFuncAttributeMaxDynamicSharedMemorySize, PROJ_SM);
    cudaFuncSetAttribute(scores_mma,  cudaFuncAttributeMaxDynamicSharedMemorySize, BIG_SM);
    cudaFuncSetAttribute(attv_mma,    cudaFuncAttributeMaxDynamicSharedMemorySize, BIG_SM);

    dim3 blk(256);
    const int Mr = Bc*NQc;   // 8192

    proj_mma<1><<<dim3((Hc*DKc)/128, Mr/128), blk, PROJ_SM>>>(q, Wq, bq, nullptr, qhh, qhl, Mr, Hc*DKc, Dc);
    proj_mma<1><<<dim3(1,            Mr/128), blk, PROJ_SM>>>(k, Wk, bk, nullptr, khh, khl, Mr, DKc, Dc);
    proj_mma<1><<<dim3(1,            Mr/128), blk, PROJ_SM>>>(v, Wv, bv, nullptr, vhh, vhl, Mr, DVc, Dc);

    transpose_v<<<dim3(NKc/32, DVc/32, Bc), dim3(32,8)>>>(vhh, vhl, vth, vtl);

    scores_mma<<<dim3(NQc/128, HBc), blk, BIG_SM>>>(qhh, qhl, khh, khl, mask, attn, tM, tL);
    reduce_rows<<<(HBc*NQc + 255)/256, 256>>>(tM, tL, rm, rli);
    attv_mma<<<dim3(NQc/128, HBc), blk, BIG_SM>>>(vth, vtl, attn, rm, rli, outh);

    proj_mma<0><<<dim3(DOc/128, Mr/128), blk, PROJ_SM>>>(outh, Wo, bo, outp, nullptr, nullptr, Mr, DOc, Hc*DVc);
}

// round 9
// speedup vs baseline: 1.3653x; 1.3653x over previous
#include <cuda_runtime.h>
#include <cuda_bf16.h>
#include <math.h>
#include <stdint.h>

typedef unsigned int u32;

#define Bc   4
#define NQc  2048
#define NKc  2048
#define Dc   1024
#define Hc   8
#define DKc  128
#define DVc  128
#define DOc  1024
#define HBc  32
#define KTILES 16

__device__ float g_qh  [(size_t)Bc*NQc*Hc*DKc];
__device__ float g_kh  [(size_t)Bc*NKc*DKc];
__device__ float g_vh  [(size_t)Bc*NKc*DVc];
__device__ float g_vT  [(size_t)Bc*DVc*NKc];
__device__ float g_outh[(size_t)Bc*NQc*Hc*DVc];
__device__ float g_tM  [(size_t)HBc*KTILES*2*NQc];
__device__ float g_tL  [(size_t)HBc*KTILES*2*NQc];
__device__ float g_rowM[(size_t)HBc*NQc];
__device__ float g_rowLi[(size_t)HBc*NQc];

// ---------------- helpers ---------------------------------------------------
__device__ __forceinline__ u32 s2u(const void* p){
    u32 a; asm("{ .reg .u64 t; cvta.to.shared.u64 t, %1; cvt.u32.u64 %0, t; }"
               : "=r"(a) : "l"(p)); return a;
}
__device__ __forceinline__ u32 pkbf2(float a, float b){
    u32 ra = (u32)__bfloat16_as_ushort(__float2bfloat16(a));
    u32 rb = (u32)__bfloat16_as_ushort(__float2bfloat16(b));
    return ra | (rb << 16);
}
__device__ __forceinline__ float bres(float x){
    return x - __bfloat162float(__float2bfloat16(x));
}
__device__ __forceinline__ void ldmx4(u32* r, u32 addr){
    asm volatile("ldmatrix.sync.aligned.m8n8.x4.shared.b16 {%0,%1,%2,%3}, [%4];"
        : "=r"(r[0]), "=r"(r[1]), "=r"(r[2]), "=r"(r[3]) : "r"(addr));
}
__device__ __forceinline__ void mma16816(float* c, const u32* a, u32 b0, u32 b1){
    asm volatile("mma.sync.aligned.m16n8k16.row.col.f32.bf16.bf16.f32 "
        "{%0,%1,%2,%3}, {%4,%5,%6,%7}, {%8,%9}, {%0,%1,%2,%3};"
        : "+f"(c[0]), "+f"(c[1]), "+f"(c[2]), "+f"(c[3])
        : "r"(a[0]), "r"(a[1]), "r"(a[2]), "r"(a[3]), "r"(b0), "r"(b1));
}

// ---- split load/convert: 128 rows x COLS fp32 -> bf16 hi/lo smem -----------
template<int COLS>
__device__ __forceinline__ void loadregs(const float* __restrict__ g, int ldA,
                                         float4* pre, int tid){
    const int PER = (128*COLS/4)/256;
#pragma unroll
    for (int i = 0; i < PER; i++){
        int idx = tid + i*256;
        int row = idx / (COLS/4);
        int c4  = (idx % (COLS/4))*4;
        pre[i] = *(const float4*)(g + (size_t)row*ldA + c4);
    }
}
template<int COLS, int STRIDE>
__device__ __forceinline__ void convert(const float4* pre, char* smHi, char* smLo, int tid){
    const int PER = (128*COLS/4)/256;
#pragma unroll
    for (int i = 0; i < PER; i++){
        int idx = tid + i*256;
        int row = idx / (COLS/4);
        int c4  = (idx % (COLS/4))*4;
        float4 v = pre[i];
        int off = (row*STRIDE + c4)*2;
        *(uint2*)(smHi+off) = make_uint2(pkbf2(v.x,v.y), pkbf2(v.z,v.w));
        *(uint2*)(smLo+off) = make_uint2(pkbf2(bres(v.x),bres(v.y)),
                                         pkbf2(bres(v.z),bres(v.w)));
    }
}
template<int COLS, int STRIDE>
__device__ __forceinline__ void ldconv(const float* __restrict__ g, int ldA,
                                       char* smHi, char* smLo, int tid){
    const int PER = (128*COLS/4)/256;
#pragma unroll
    for (int i = 0; i < PER; i++){
        int idx = tid + i*256;
        int row = idx / (COLS/4);
        int c4  = (idx % (COLS/4))*4;
        float4 v = *(const float4*)(g + (size_t)row*ldA + c4);
        int off = (row*STRIDE + c4)*2;
        *(uint2*)(smHi+off) = make_uint2(pkbf2(v.x,v.y), pkbf2(v.z,v.w));
        *(uint2*)(smLo+off) = make_uint2(pkbf2(bres(v.x),bres(v.y)),
                                         pkbf2(bres(v.z),bres(v.w)));
    }
}

// One k-step (k=16): warp computes 32x64 using split bf16x3.
template<int SA, int SB>
__device__ __forceinline__ void wstep(u32 Ah, u32 Al, u32 Bh, u32 Bl,
                                      int ks, int warp_m, int warp_n, int lane,
                                      float c[2][8][4]){
    const int rsel = lane & 15, ksel = (lane >> 4) << 3;
    const int kb = ks*16 + ksel;
    u32 ah[2][4], al[2][4], bh[4][4], bl[4][4];
#pragma unroll
    for (int mt = 0; mt < 2; mt++){
        u32 off = (u32)((warp_m*32 + mt*16 + rsel)*SA + kb)*2;
        ldmx4(ah[mt], Ah + off);
        ldmx4(al[mt], Al + off);
    }
#pragma unroll
    for (int p = 0; p < 4; p++){
        u32 off = (u32)((warp_n*64 + p*16 + rsel)*SB + kb)*2;
        ldmx4(bh[p], Bh + off);
        ldmx4(bl[p], Bl + off);
    }
#pragma unroll
    for (int mt = 0; mt < 2; mt++)
#pragma unroll
        for (int nt = 0; nt < 8; nt++){
            int p = nt >> 1, s = nt & 1;
            u32 b0h = bh[p][s], b1h = bh[p][2+s];
            u32 b0l = bl[p][s], b1l = bl[p][2+s];
            mma16816(c[mt][nt], ah[mt], b0h, b1h);
            mma16816(c[mt][nt], ah[mt], b0l, b1l);
            mma16816(c[mt][nt], al[mt], b0h, b1h);
        }
}

// ---------------------------------------------------------------------------
// proj: C[M,N] = A[M,K] @ W[N,K]^T + bias. 128x128 CTA tile, K chunks of 64,
// double-buffered smem, register-prefetched, ONE sync per chunk.
// ---------------------------------------------------------------------------
#define PSTR 72
#define PTILE (128*PSTR*2)
__global__ void __launch_bounds__(256) proj_mma(
    const float* __restrict__ A, const float* __restrict__ W,
    const float* __restrict__ bias, float* __restrict__ C,
    int M, int N, int K)
{
    extern __shared__ char sm[];
    u32 sb = s2u(sm);
    const int tid = threadIdx.x, lane = tid & 31, wid = tid >> 5;
    const int warp_m = wid & 3, warp_n = wid >> 2;
    const int n0 = blockIdx.x << 7, m0 = blockIdx.y << 7;

    // buffers: [buf][ A_hi, A_lo, W_hi, W_lo ]
    char* Ahp[2] = { sm,           sm + 4*PTILE };
    char* Alp[2] = { sm +   PTILE, sm + 5*PTILE };
    char* Bhp[2] = { sm + 2*PTILE, sm + 6*PTILE };
    char* Blp[2] = { sm + 3*PTILE, sm + 7*PTILE };

    float c[2][8][4];
#pragma unroll
    for (int i=0;i<2;i++) for (int j=0;j<8;j++) for (int q=0;q<4;q++) c[i][j][q]=0.f;

    float4 preA[8], preW[8];
    const int NC = K/64;

    loadregs<64>(A + (size_t)m0*K, K, preA, tid);
    loadregs<64>(W + (size_t)n0*K, K, preW, tid);
    convert<64,PSTR>(preA, Ahp[0], Alp[0], tid);
    convert<64,PSTR>(preW, Bhp[0], Blp[0], tid);
    if (NC > 1){
        loadregs<64>(A + (size_t)m0*K + 64, K, preA, tid);
        loadregs<64>(W + (size_t)n0*K + 64, K, preW, tid);
    }
    __syncthreads();

    for (int kc = 0; kc < NC; kc++){
        int cur = kc & 1, nxt = cur ^ 1;
        if (kc + 1 < NC){
            convert<64,PSTR>(preA, Ahp[nxt], Alp[nxt], tid);
            convert<64,PSTR>(preW, Bhp[nxt], Blp[nxt], tid);
        }
        if (kc + 2 < NC){
            loadregs<64>(A + (size_t)m0*K + (kc+2)*64, K, preA, tid);
            loadregs<64>(W + (size_t)n0*K + (kc+2)*64, K, preW, tid);
        }
        u32 Ah = sb + (u32)(Ahp[cur]-sm), Al = sb + (u32)(Alp[cur]-sm);
        u32 Bh = sb + (u32)(Bhp[cur]-sm), Bl = sb + (u32)(Blp[cur]-sm);
#pragma unroll
        for (int ks = 0; ks < 4; ks++)
            wstep<PSTR,PSTR>(Ah, Al, Bh, Bl, ks, warp_m, warp_n, lane, c);
        __syncthreads();
    }

#pragma unroll
    for (int mt = 0; mt < 2; mt++)
#pragma unroll
        for (int rh = 0; rh < 2; rh++){
            int row = m0 + warp_m*32 + mt*16 + rh*8 + (lane >> 2);
#pragma unroll
            for (int nt = 0; nt < 8; nt++){
                int col = n0 + warp_n*64 + nt*8 + ((lane & 3) << 1);
                float2 o;
                o.x = c[mt][nt][rh*2+0] + __ldg(bias + col);
                o.y = c[mt][nt][rh*2+1] + __ldg(bias + col + 1);
                *(float2*)(C + (size_t)row*N + col) = o;
            }
        }
}

// ---------------------------------------------------------------------------
// scores: per (q-tile 128, hb): S = scale*(Q@K^T)+mask over 16 k-tiles.
// K double-buffered (Q resident), ONE sync per tile.
// ---------------------------------------------------------------------------
#define SSTR 136
#define STILE (128*SSTR*2)
__global__ void __launch_bounds__(256) scores_mma(
    const float* __restrict__ qh, const float* __restrict__ kh,
    const float* __restrict__ mask, float* __restrict__ attn,
    float* __restrict__ tM, float* __restrict__ tL)
{
    extern __shared__ char sm[];
    u32 sb = s2u(sm);
    const int tid = threadIdx.x, lane = tid & 31, wid = tid >> 5;
    const int warp_m = wid & 3, warp_n = wid >> 2;
    const int q0 = blockIdx.x << 7;
    const int hb = blockIdx.y, b = hb >> 3, h = hb & 7;

    char* Qhp = sm;            char* Qlp = sm + STILE;
    char* Khp[2] = { sm + 2*STILE, sm + 4*STILE };
    char* Klp[2] = { sm + 3*STILE, sm + 5*STILE };
    const u32 Qh = sb, Ql = sb + STILE;

    const float* qbase = qh + (size_t)(b*NQc + q0)*Dc + h*DKc;
    const float* kbase = kh + (size_t)b*NKc*DKc;
    ldconv<128,SSTR>(qbase, Dc, Qhp, Qlp, tid);

    float4 preK[16];
    loadregs<128>(kbase, DKc, preK, tid);
    convert<128,SSTR>(preK, Khp[0], Klp[0], tid);
    loadregs<128>(kbase + (size_t)128*DKc, DKc, preK, tid);
    __syncthreads();

    const float scale = 0.08838834764831845f;

    for (int kt = 0; kt < KTILES; kt++){
        int cur = kt & 1, nxt = cur ^ 1;
        if (kt + 1 < KTILES)
            convert<128,SSTR>(preK, Khp[nxt], Klp[nxt], tid);
        if (kt + 2 < KTILES)
            loadregs<128>(kbase + (size_t)((kt+2)*128)*DKc, DKc, preK, tid);

        u32 Kh = sb + (u32)(Khp[cur]-sm), Kl = sb + (u32)(Klp[cur]-sm);
        float c[2][8][4];
#pragma unroll
        for (int i=0;i<2;i++) for (int j=0;j<8;j++) for (int q=0;q<4;q++) c[i][j][q]=0.f;
#pragma unroll
        for (int ks = 0; ks < 8; ks++)
            wstep<SSTR,SSTR>(Qh, Ql, Kh, Kl, ks, warp_m, warp_n, lane, c);

        // epilogue: scale + mask, write raw S, row stats (no smem use)
#pragma unroll
        for (int mt = 0; mt < 2; mt++)
#pragma unroll
            for (int rh = 0; rh < 2; rh++){
                int row = q0 + warp_m*32 + mt*16 + rh*8 + (lane >> 2);
                const float* mrow = mask + ((size_t)b*NQc + row)*NKc + kt*128;
                float* arow = attn + ((size_t)(h*Bc + b)*NQc + row)*NKc + kt*128;
                float mx = -1e30f, le = 0.f;
#pragma unroll
                for (int nt = 0; nt < 8; nt++){
                    int col = warp_n*64 + nt*8 + ((lane & 3) << 1);
                    float2 mv = *(const float2*)(mrow + col);
                    float s0 = fmaf(c[mt][nt][rh*2+0], scale, mv.x);
                    float s1 = fmaf(c[mt][nt][rh*2+1], scale, mv.y);
                    *(float2*)(arow + col) = make_float2(s0, s1);
                    float m2 = fmaxf(s0, s1);
                    float nm = fmaxf(mx, m2);
                    le = le*__expf(mx - nm) + __expf(s0 - nm) + __expf(s1 - nm);
                    mx = nm;
                }
#pragma unroll
                for (int off = 1; off <= 2; off <<= 1){
                    float mo = __shfl_xor_sync(0xFFFFFFFFu, mx, off);
                    float lo = __shfl_xor_sync(0xFFFFFFFFu, le, off);
                    float nm = fmaxf(mx, mo);
                    le = le*__expf(mx - nm) + lo*__expf(mo - nm);
                    mx = nm;
                }
                if ((lane & 3) == 0){
                    size_t o = ((size_t)hb*KTILES*2 + kt*2 + warp_n)*NQc + row;
                    tM[o] = mx; tL[o] = le;
                }
            }
        __syncthreads();
    }
}

// per-row combine over 32 slots (16 tiles x 2 warp halves)
__global__ void reduce_rows(const float* __restrict__ tM, const float* __restrict__ tL,
                            float* __restrict__ rowM, float* __restrict__ rowLi)
{
    int idx = blockIdx.x * blockDim.x + threadIdx.x;
    if (idx >= HBc*NQc) return;
    int bz = idx / NQc, row = idx % NQc;
    float M = -1e30f;
#pragma unroll
    for (int t = 0; t < KTILES*2; t++)
        M = fmaxf(M, tM[(size_t)(bz*KTILES*2 + t)*NQc + row]);
    float L = 0.f;
#pragma unroll
    for (int t = 0; t < KTILES*2; t++)
        L += tL[(size_t)(bz*KTILES*2 + t)*NQc + row]
           * __expf(tM[(size_t)(bz*KTILES*2 + t)*NQc + row] - M);
    rowM[idx] = M; rowLi[idx] = 1.0f / L;
}

// vh [b,k,d] -> vT [b,d,k]
__global__ void transpose_v(const float* __restrict__ vh, float* __restrict__ vT){
    __shared__ float t[32][33];
    int b = blockIdx.z;
    int k0 = blockIdx.x*32, d0 = blockIdx.y*32;
    int x = threadIdx.x, y = threadIdx.y;
#pragma unroll
    for (int i = 0; i < 32; i += 8)
        t[y+i][x] = vh[(size_t)(b*NKc + k0 + y + i)*DVc + d0 + x];
    __syncthreads();
#pragma unroll
    for (int i = 0; i < 32; i += 8)
        vT[((size_t)b*DVc + d0 + y + i)*NKc + k0 + x] = t[x][y+i];
}

// ---------------------------------------------------------------------------
// attv: normalize P (write back), outh = P @ V via vT. P register-prefetched.
// (same as R7 — smem too small for full double buffering here)
// ---------------------------------------------------------------------------
__global__ void __launch_bounds__(256) attv_mma(
    const float* __restrict__ vT, float* __restrict__ attn,
    const float* __restrict__ rowM, const float* __restrict__ rowLi,
    float* __restrict__ outh)
{
    extern __shared__ char sm[];
    __shared__ float Ms[128], Li[128];
    u32 sb = s2u(sm);
    const int tid = threadIdx.x, lane = tid & 31, wid = tid >> 5;
    const int warp_m = wid & 3, warp_n = wid >> 2;
    const int q0 = blockIdx.x << 7;
    const int hb = blockIdx.y, b = hb >> 3, h = hb & 7;

    char* Php = sm;            char* Plp = sm + STILE;
    char* Vhp = sm + 2*STILE;  char* Vlp = sm + 3*STILE;
    const u32 Ph = sb, Pl = sb + STILE, Vh = sb + 2*STILE, Vl = sb + 3*STILE;

    if (tid < 128){
        int gi = hb*NQc + q0 + tid;
        Ms[tid] = rowM[gi];
        Li[tid] = rowLi[gi];
    }

    float* abase = attn + ((size_t)(h*Bc + b)*NQc + q0)*NKc;
    const float* vbase = vT + (size_t)b*DVc*NKc;

    float4 preP[16];
    loadregs<128>(abase, NKc, preP, tid);
    __syncthreads();

    float c[2][8][4];
#pragma unroll
    for (int i=0;i<2;i++) for (int j=0;j<8;j++) for (int q=0;q<4;q++) c[i][j][q]=0.f;

    for (int kt = 0; kt < KTILES; kt++){
        // normalize prefetched P chunk, write back, stage bf16 hi/lo
#pragma unroll
        for (int i = 0; i < 16; i++){
            int idx = tid + i*256;
            int row = idx >> 5, c4 = (idx & 31) << 2;
            float4 s = preP[i];
            float mm = Ms[row], li = Li[row];
            float4 p;
            p.x = __expf(s.x - mm)*li; p.y = __expf(s.y - mm)*li;
            p.z = __expf(s.z - mm)*li; p.w = __expf(s.w - mm)*li;
            *(float4*)(abase + (size_t)row*NKc + kt*128 + c4) = p;
            int off = (row*SSTR + c4)*2;
            *(uint2*)(Php+off) = make_uint2(pkbf2(p.x,p.y), pkbf2(p.z,p.w));
            *(uint2*)(Plp+off) = make_uint2(pkbf2(bres(p.x),bres(p.y)),
                                            pkbf2(bres(p.z),bres(p.w)));
        }
        ldconv<128,SSTR>(vbase + kt*128, NKc, Vhp, Vlp, tid);
        __syncthreads();
        if (kt + 1 < KTILES)
            loadregs<128>(abase + (kt+1)*128, NKc, preP, tid);
#pragma unroll
        for (int ks = 0; ks < 8; ks++)
            wstep<SSTR,SSTR>(Ph, Pl, Vh, Vl, ks, warp_m, warp_n, lane, c);
        __syncthreads();
    }

#pragma unroll
    for (int mt = 0; mt < 2; mt++)
#pragma unroll
        for (int rh = 0; rh < 2; rh++){
            int row = q0 + warp_m*32 + mt*16 + rh*8 + (lane >> 2);
            float* op = outh + (size_t)(b*NQc + row)*(Hc*DVc) + h*DVc;
#pragma unroll
            for (int nt = 0; nt < 8; nt++){
                int col = warp_n*64 + nt*8 + ((lane & 3) << 1);
                *(float2*)(op + col) = make_float2(c[mt][nt][rh*2+0], c[mt][nt][rh*2+1]);
            }
        }
}

// ---------------------------------------------------------------------------
extern "C" void kernel_launch(void* const* d_in, const int* in_sizes, int n_in,
                              void* d_out, int out_size)
{
    const float* q    = (const float*)d_in[0];
    const float* k    = (const float*)d_in[1];
    const float* v    = (const float*)d_in[2];
    const float* mask = (const float*)d_in[3];
    const float* Wq   = (const float*)d_in[4];
    const float* bq   = (const float*)d_in[5];
    const float* Wk   = (const float*)d_in[6];
    const float* bk   = (const float*)d_in[7];
    const float* Wv   = (const float*)d_in[8];
    const float* bv   = (const float*)d_in[9];
    const float* Wo   = (const float*)d_in[10];
    const float* bo   = (const float*)d_in[11];

    float* attn = (float*)d_out;
    float* outp = attn + (size_t)HBc*NQc*NKc;

    float *qh,*kh,*vh,*vT,*outh,*tM,*tL,*rm,*rli;
    cudaGetSymbolAddress((void**)&qh,   g_qh);
    cudaGetSymbolAddress((void**)&kh,   g_kh);
    cudaGetSymbolAddress((void**)&vh,   g_vh);
    cudaGetSymbolAddress((void**)&vT,   g_vT);
    cudaGetSymbolAddress((void**)&outh, g_outh);
    cudaGetSymbolAddress((void**)&tM,   g_tM);
    cudaGetSymbolAddress((void**)&tL,   g_tL);
    cudaGetSymbolAddress((void**)&rm,   g_rowM);
    cudaGetSymbolAddress((void**)&rli,  g_rowLi);

    const int PROJ_SM = 8*PTILE;           // 147456
    const int SC_SM   = 6*STILE;           // 208896
    const int AT_SM   = 4*STILE;           // 139264
    cudaFuncSetAttribute(proj_mma,   cudaFuncAttributeMaxDynamicSharedMemorySize, PROJ_SM);
    cudaFuncSetAttribute(scores_mma, cudaFuncAttributeMaxDynamicSharedMemorySize, SC_SM);
    cudaFuncSetAttribute(attv_mma,   cudaFuncAttributeMaxDynamicSharedMemorySize, AT_SM);

    dim3 blk(256);
    const int Mr = Bc*NQc;   // 8192

    proj_mma<<<dim3((Hc*DKc)/128, Mr/128), blk, PROJ_SM>>>(q, Wq, bq, qh, Mr, Hc*DKc, Dc);
    proj_mma<<<dim3(1,            Mr/128), blk, PROJ_SM>>>(k, Wk, bk, kh, Mr, DKc, Dc);
    proj_mma<<<dim3(1,            Mr/128), blk, PROJ_SM>>>(v, Wv, bv, vh, Mr, DVc, Dc);

    transpose_v<<<dim3(NKc/32, DVc/32, Bc), dim3(32,8)>>>(vh, vT);

    scores_mma<<<dim3(NQc/128, HBc), blk, SC_SM>>>(qh, kh, mask, attn, tM, tL);
    reduce_rows<<<(HBc*NQc + 255)/256, 256>>>(tM, tL, rm, rli);
    attv_mma<<<dim3(NQc/128, HBc), blk, AT_SM>>>(vT, attn, rm, rli, outh);

    proj_mma<<<dim3(DOc/128, Mr/128), blk, PROJ_SM>>>(outh, Wo, bo, outp, Mr, DOc, Hc*DVc);
}

// round 10
// speedup vs baseline: 1.4160x; 1.0372x over previous
#include <cuda_runtime.h>
#include <cuda_bf16.h>
#include <math.h>
#include <stdint.h>

typedef unsigned int u32;

#define Bc   4
#define NQc  2048
#define NKc  2048
#define Dc   1024
#define Hc   8
#define DKc  128
#define DVc  128
#define DOc  1024
#define HBc  32
#define KTILES 16

__device__ float g_qh  [(size_t)Bc*NQc*Hc*DKc];
__device__ float g_kh  [(size_t)Bc*NKc*DKc];
__device__ float g_vh  [(size_t)Bc*NKc*DVc];
__device__ float g_vT  [(size_t)Bc*DVc*NKc];
__device__ float g_outh[(size_t)Bc*NQc*Hc*DVc];

// ---------------- helpers ---------------------------------------------------
__device__ __forceinline__ u32 s2u(const void* p){
    u32 a; asm("{ .reg .u64 t; cvta.to.shared.u64 t, %1; cvt.u32.u64 %0, t; }"
               : "=r"(a) : "l"(p)); return a;
}
__device__ __forceinline__ u32 pkbf2(float a, float b){
    u32 ra = (u32)__bfloat16_as_ushort(__float2bfloat16(a));
    u32 rb = (u32)__bfloat16_as_ushort(__float2bfloat16(b));
    return ra | (rb << 16);
}
__device__ __forceinline__ float bres(float x){
    return x - __bfloat162float(__float2bfloat16(x));
}
__device__ __forceinline__ void ldmx4(u32* r, u32 addr){
    asm volatile("ldmatrix.sync.aligned.m8n8.x4.shared.b16 {%0,%1,%2,%3}, [%4];"
        : "=r"(r[0]), "=r"(r[1]), "=r"(r[2]), "=r"(r[3]) : "r"(addr));
}
__device__ __forceinline__ void mma16816(float* c, const u32* a, u32 b0, u32 b1){
    asm volatile("mma.sync.aligned.m16n8k16.row.col.f32.bf16.bf16.f32 "
        "{%0,%1,%2,%3}, {%4,%5,%6,%7}, {%8,%9}, {%0,%1,%2,%3};"
        : "+f"(c[0]), "+f"(c[1]), "+f"(c[2]), "+f"(c[3])
        : "r"(a[0]), "r"(a[1]), "r"(a[2]), "r"(a[3]), "r"(b0), "r"(b1));
}

// ---- split load/convert: 128 rows x COLS fp32 -> bf16 hi/lo smem -----------
template<int COLS>
__device__ __forceinline__ void loadregs(const float* __restrict__ g, int ldA,
                                         float4* pre, int tid){
    const int PER = (128*COLS/4)/256;
#pragma unroll
    for (int i = 0; i < PER; i++){
        int idx = tid + i*256;
        int row = idx / (COLS/4);
        int c4  = (idx % (COLS/4))*4;
        pre[i] = *(const float4*)(g + (size_t)row*ldA + c4);
    }
}
template<int COLS, int STRIDE>
__device__ __forceinline__ void convert(const float4* pre, char* smHi, char* smLo, int tid){
    const int PER = (128*COLS/4)/256;
#pragma unroll
    for (int i = 0; i < PER; i++){
        int idx = tid + i*256;
        int row = idx / (COLS/4);
        int c4  = (idx % (COLS/4))*4;
        float4 v = pre[i];
        int off = (row*STRIDE + c4)*2;
        *(uint2*)(smHi+off) = make_uint2(pkbf2(v.x,v.y), pkbf2(v.z,v.w));
        *(uint2*)(smLo+off) = make_uint2(pkbf2(bres(v.x),bres(v.y)),
                                         pkbf2(bres(v.z),bres(v.w)));
    }
}
template<int COLS, int STRIDE>
__device__ __forceinline__ void ldconv(const float* __restrict__ g, int ldA,
                                       char* smHi, char* smLo, int tid){
    const int PER = (128*COLS/4)/256;
#pragma unroll
    for (int i = 0; i < PER; i++){
        int idx = tid + i*256;
        int row = idx / (COLS/4);
        int c4  = (idx % (COLS/4))*4;
        float4 v = *(const float4*)(g + (size_t)row*ldA + c4);
        int off = (row*STRIDE + c4)*2;
        *(uint2*)(smHi+off) = make_uint2(pkbf2(v.x,v.y), pkbf2(v.z,v.w));
        *(uint2*)(smLo+off) = make_uint2(pkbf2(bres(v.x),bres(v.y)),
                                         pkbf2(bres(v.z),bres(v.w)));
    }
}

// One k-step (k=16): warp computes 32x64 using split bf16x3.
template<int SA, int SB>
__device__ __forceinline__ void wstep(u32 Ah, u32 Al, u32 Bh, u32 Bl,
                                      int ks, int warp_m, int warp_n, int lane,
                                      float c[2][8][4]){
    const int rsel = lane & 15, ksel = (lane >> 4) << 3;
    const int kb = ks*16 + ksel;
    u32 ah[2][4], al[2][4], bh[4][4], bl[4][4];
#pragma unroll
    for (int mt = 0; mt < 2; mt++){
        u32 off = (u32)((warp_m*32 + mt*16 + rsel)*SA + kb)*2;
        ldmx4(ah[mt], Ah + off);
        ldmx4(al[mt], Al + off);
    }
#pragma unroll
    for (int p = 0; p < 4; p++){
        u32 off = (u32)((warp_n*64 + p*16 + rsel)*SB + kb)*2;
        ldmx4(bh[p], Bh + off);
        ldmx4(bl[p], Bl + off);
    }
#pragma unroll
    for (int mt = 0; mt < 2; mt++)
#pragma unroll
        for (int nt = 0; nt < 8; nt++){
            int p = nt >> 1, s = nt & 1;
            u32 b0h = bh[p][s], b1h = bh[p][2+s];
            u32 b0l = bl[p][s], b1l = bl[p][2+s];
            mma16816(c[mt][nt], ah[mt], b0h, b1h);
            mma16816(c[mt][nt], ah[mt], b0l, b1l);
            mma16816(c[mt][nt], al[mt], b0h, b1h);
        }
}

// ---------------------------------------------------------------------------
// proj: C[M,N] = A[M,K] @ W[N,K]^T + bias (R7 form: register-prefetched).
// ---------------------------------------------------------------------------
#define PSTR 72
#define PTILE (128*PSTR*2)
__global__ void __launch_bounds__(256) proj_mma(
    const float* __restrict__ A, const float* __restrict__ W,
    const float* __restrict__ bias, float* __restrict__ C,
    int M, int N, int K)
{
    extern __shared__ char sm[];
    u32 sb = s2u(sm);
    const int tid = threadIdx.x, lane = tid & 31, wid = tid >> 5;
    const int warp_m = wid & 3, warp_n = wid >> 2;
    const int n0 = blockIdx.x << 7, m0 = blockIdx.y << 7;

    char* Ahp = sm;            char* Alp = sm + PTILE;
    char* Bhp = sm + 2*PTILE;  char* Blp = sm + 3*PTILE;
    const u32 Ah = sb, Al = sb + PTILE, Bh = sb + 2*PTILE, Bl = sb + 3*PTILE;

    float c[2][8][4];
#pragma unroll
    for (int i=0;i<2;i++) for (int j=0;j<8;j++) for (int q=0;q<4;q++) c[i][j][q]=0.f;

    float4 preA[8], preW[8];
    loadregs<64>(A + (size_t)m0*K, K, preA, tid);
    loadregs<64>(W + (size_t)n0*K, K, preW, tid);

    const int NC = K/64;
    for (int kc = 0; kc < NC; kc++){
        convert<64,PSTR>(preA, Ahp, Alp, tid);
        convert<64,PSTR>(preW, Bhp, Blp, tid);
        __syncthreads();
        if (kc + 1 < NC){
            loadregs<64>(A + (size_t)m0*K + (kc+1)*64, K, preA, tid);
            loadregs<64>(W + (size_t)n0*K + (kc+1)*64, K, preW, tid);
        }
#pragma unroll
        for (int ks = 0; ks < 4; ks++)
            wstep<PSTR,PSTR>(Ah, Al, Bh, Bl, ks, warp_m, warp_n, lane, c);
        __syncthreads();
    }

#pragma unroll
    for (int mt = 0; mt < 2; mt++)
#pragma unroll
        for (int rh = 0; rh < 2; rh++){
            int row = m0 + warp_m*32 + mt*16 + rh*8 + (lane >> 2);
#pragma unroll
            for (int nt = 0; nt < 8; nt++){
                int col = n0 + warp_n*64 + nt*8 + ((lane & 3) << 1);
                float2 o;
                o.x = c[mt][nt][rh*2+0] + __ldg(bias + col);
                o.y = c[mt][nt][rh*2+1] + __ldg(bias + col + 1);
                *(float2*)(C + (size_t)row*N + col) = o;
            }
        }
}

// vh [b,k,d] -> vT [b,d,k]
__global__ void transpose_v(const float* __restrict__ vh, float* __restrict__ vT){
    __shared__ float t[32][33];
    int b = blockIdx.z;
    int k0 = blockIdx.x*32, d0 = blockIdx.y*32;
    int x = threadIdx.x, y = threadIdx.y;
#pragma unroll
    for (int i = 0; i < 32; i += 8)
        t[y+i][x] = vh[(size_t)(b*NKc + k0 + y + i)*DVc + d0 + x];
    __syncthreads();
#pragma unroll
    for (int i = 0; i < 32; i += 8)
        vT[((size_t)b*DVc + d0 + y + i)*NKc + k0 + x] = t[x][y+i];
}

// ---------------------------------------------------------------------------
// fused attention: per (q-tile 128, hb) CTA:
//   Phase 1: 16 k-tiles of raw S = scale*(Q@K^T)+mask -> attn; running row
//            stats carried in registers.
//   In-CTA stat combine -> Ms / Li (no gmem, no extra kernel).
//   Phase 2: re-read raw S (L2-hot), normalize, write P, accumulate P@V.
// ---------------------------------------------------------------------------
#define SSTR 136
#define STILE (128*SSTR*2)
__global__ void __launch_bounds__(256) fused_attn(
    const float* __restrict__ qh, const float* __restrict__ kh,
    const float* __restrict__ vT, const float* __restrict__ mask,
    float* __restrict__ attn, float* __restrict__ outh)
{
    extern __shared__ char sm[];
    __shared__ float Ms[128], Li[128];
    __shared__ float sM2[2][128], sL2[2][128];
    u32 sb = s2u(sm);
    const int tid = threadIdx.x, lane = tid & 31, wid = tid >> 5;
    const int warp_m = wid & 3, warp_n = wid >> 2;
    const int q0 = blockIdx.x << 7;
    const int hb = blockIdx.y, b = hb >> 3, h = hb & 7;

    char* Ahp = sm;            char* Alp = sm + STILE;   // Q, later P
    char* Bhp = sm + 2*STILE;  char* Blp = sm + 3*STILE; // K, later V
    const u32 Ah = sb, Al = sb + STILE, Bh = sb + 2*STILE, Bl = sb + 3*STILE;

    const float* qbase = qh + (size_t)(b*NQc + q0)*Dc + h*DKc;
    const float* kbase = kh + (size_t)b*NKc*DKc;
    const float* vbase = vT + (size_t)b*DVc*NKc;
    float* abase = attn + ((size_t)(h*Bc + b)*NQc + q0)*NKc;

    // ---- Phase 1: scores ----
    ldconv<128,SSTR>(qbase, Dc, Ahp, Alp, tid);

    float4 preK[16];
    loadregs<128>(kbase, DKc, preK, tid);

    const float scale = 0.08838834764831845f;
    float rm_[2][2], rl_[2][2];
#pragma unroll
    for (int i=0;i<2;i++)
#pragma unroll
        for (int j=0;j<2;j++){ rm_[i][j] = -1e30f; rl_[i][j] = 0.f; }

    for (int kt = 0; kt < KTILES; kt++){
        convert<128,SSTR>(preK, Bhp, Blp, tid);
        __syncthreads();
        if (kt + 1 < KTILES)
            loadregs<128>(kbase + (size_t)((kt+1)*128)*DKc, DKc, preK, tid);

        float c[2][8][4];
#pragma unroll
        for (int i=0;i<2;i++) for (int j=0;j<8;j++) for (int q=0;q<4;q++) c[i][j][q]=0.f;
#pragma unroll
        for (int ks = 0; ks < 8; ks++)
            wstep<SSTR,SSTR>(Ah, Al, Bh, Bl, ks, warp_m, warp_n, lane, c);

#pragma unroll
        for (int mt = 0; mt < 2; mt++)
#pragma unroll
            for (int rh = 0; rh < 2; rh++){
                int row = q0 + warp_m*32 + mt*16 + rh*8 + (lane >> 2);
                const float* mrow = mask + ((size_t)b*NQc + row)*NKc + kt*128;
                float* arow = abase + (size_t)(row - q0)*NKc + kt*128;
                float mx = rm_[mt][rh], le = rl_[mt][rh];
#pragma unroll
                for (int nt = 0; nt < 8; nt++){
                    int col = warp_n*64 + nt*8 + ((lane & 3) << 1);
                    float2 mv = *(const float2*)(mrow + col);
                    float s0 = fmaf(c[mt][nt][rh*2+0], scale, mv.x);
                    float s1 = fmaf(c[mt][nt][rh*2+1], scale, mv.y);
                    *(float2*)(arow + col) = make_float2(s0, s1);
                    float m2 = fmaxf(s0, s1);
                    float nm = fmaxf(mx, m2);
                    le = le*__expf(mx - nm) + __expf(s0 - nm) + __expf(s1 - nm);
                    mx = nm;
                }
                rm_[mt][rh] = mx; rl_[mt][rh] = le;
            }
        __syncthreads();
    }

    // ---- stat combine (lane quad -> warp_n halves -> per row) ----
#pragma unroll
    for (int mt = 0; mt < 2; mt++)
#pragma unroll
        for (int rh = 0; rh < 2; rh++){
            float mx = rm_[mt][rh], le = rl_[mt][rh];
#pragma unroll
            for (int off = 1; off <= 2; off <<= 1){
                float mo = __shfl_xor_sync(0xFFFFFFFFu, mx, off);
                float lo = __shfl_xor_sync(0xFFFFFFFFu, le, off);
                float nm = fmaxf(mx, mo);
                le = le*__expf(mx - nm) + lo*__expf(mo - nm);
                mx = nm;
            }
            int rowl = warp_m*32 + mt*16 + rh*8 + (lane >> 2);
            if ((lane & 3) == 0){
                sM2[warp_n][rowl] = mx;
                sL2[warp_n][rowl] = le;
            }
        }
    __syncthreads();
    if (tid < 128){
        float m0 = sM2[0][tid], m1 = sM2[1][tid];
        float M = fmaxf(m0, m1);
        float L = sL2[0][tid]*__expf(m0 - M) + sL2[1][tid]*__expf(m1 - M);
        Ms[tid] = M; Li[tid] = 1.0f / L;
    }
    __syncthreads();

    // ---- Phase 2: P@V ----
    float4 preP[16];
    loadregs<128>(abase, NKc, preP, tid);

    float c[2][8][4];
#pragma unroll
    for (int i=0;i<2;i++) for (int j=0;j<8;j++) for (int q=0;q<4;q++) c[i][j][q]=0.f;

    for (int kt = 0; kt < KTILES; kt++){
        // normalize prefetched raw S chunk -> P: write back, stage bf16 hi/lo
#pragma unroll
        for (int i = 0; i < 16; i++){
            int idx = tid + i*256;
            int row = idx >> 5, c4 = (idx & 31) << 2;
            float4 s = preP[i];
            float mm = Ms[row], li = Li[row];
            float4 p;
            p.x = __expf(s.x - mm)*li; p.y = __expf(s.y - mm)*li;
            p.z = __expf(s.z - mm)*li; p.w = __expf(s.w - mm)*li;
            *(float4*)(abase + (size_t)row*NKc + kt*128 + c4) = p;
            int off = (row*SSTR + c4)*2;
            *(uint2*)(Ahp+off) = make_uint2(pkbf2(p.x,p.y), pkbf2(p.z,p.w));
            *(uint2*)(Alp+off) = make_uint2(pkbf2(bres(p.x),bres(p.y)),
                                            pkbf2(bres(p.z),bres(p.w)));
        }
        ldconv<128,SSTR>(vbase + kt*128, NKc, Bhp, Blp, tid);
        __syncthreads();
        if (kt + 1 < KTILES)
            loadregs<128>(abase + (kt+1)*128, NKc, preP, tid);
#pragma unroll
        for (int ks = 0; ks < 8; ks++)
            wstep<SSTR,SSTR>(Ah, Al, Bh, Bl, ks, warp_m, warp_n, lane, c);
        __syncthreads();
    }

#pragma unroll
    for (int mt = 0; mt < 2; mt++)
#pragma unroll
        for (int rh = 0; rh < 2; rh++){
            int row = q0 + warp_m*32 + mt*16 + rh*8 + (lane >> 2);
            float* op = outh + (size_t)(b*NQc + row)*(Hc*DVc) + h*DVc;
#pragma unroll
            for (int nt = 0; nt < 8; nt++){
                int col = warp_n*64 + nt*8 + ((lane & 3) << 1);
                *(float2*)(op + col) = make_float2(c[mt][nt][rh*2+0], c[mt][nt][rh*2+1]);
            }
        }
}

// ---------------------------------------------------------------------------
extern "C" void kernel_launch(void* const* d_in, const int* in_sizes, int n_in,
                              void* d_out, int out_size)
{
    const float* q    = (const float*)d_in[0];
    const float* k    = (const float*)d_in[1];
    const float* v    = (const float*)d_in[2];
    const float* mask = (const float*)d_in[3];
    const float* Wq   = (const float*)d_in[4];
    const float* bq   = (const float*)d_in[5];
    const float* Wk   = (const float*)d_in[6];
    const float* bk   = (const float*)d_in[7];
    const float* Wv   = (const float*)d_in[8];
    const float* bv   = (const float*)d_in[9];
    const float* Wo   = (const float*)d_in[10];
    const float* bo   = (const float*)d_in[11];

    float* attn = (float*)d_out;
    float* outp = attn + (size_t)HBc*NQc*NKc;

    float *qh,*kh,*vh,*vT,*outh;
    cudaGetSymbolAddress((void**)&qh,   g_qh);
    cudaGetSymbolAddress((void**)&kh,   g_kh);
    cudaGetSymbolAddress((void**)&vh,   g_vh);
    cudaGetSymbolAddress((void**)&vT,   g_vT);
    cudaGetSymbolAddress((void**)&outh, g_outh);

    const int PROJ_SM = 4*PTILE;           // 73728
    const int FUS_SM  = 4*STILE;           // 139264
    cudaFuncSetAttribute(proj_mma,   cudaFuncAttributeMaxDynamicSharedMemorySize, PROJ_SM);
    cudaFuncSetAttribute(fused_attn, cudaFuncAttributeMaxDynamicSharedMemorySize, FUS_SM);

    dim3 blk(256);
    const int Mr = Bc*NQc;   // 8192

    proj_mma<<<dim3((Hc*DKc)/128, Mr/128), blk, PROJ_SM>>>(q, Wq, bq, qh, Mr, Hc*DKc, Dc);
    proj_mma<<<dim3(1,            Mr/128), blk, PROJ_SM>>>(k, Wk, bk, kh, Mr, DKc, Dc);
    proj_mma<<<dim3(1,            Mr/128), blk, PROJ_SM>>>(v, Wv, bv, vh, Mr, DVc, Dc);

    transpose_v<<<dim3(NKc/32, DVc/32, Bc), dim3(32,8)>>>(vh, vT);

    fused_attn<<<dim3(NQc/128, HBc), blk, FUS_SM>>>(qh, kh, vT, mask, attn, outh);

    proj_mma<<<dim3(DOc/128, Mr/128), blk, PROJ_SM>>>(outh, Wo, bo, outp, Mr, DOc, Hc*DVc);
}

// round 11
// speedup vs baseline: 1.4328x; 1.0119x over previous
#include <cuda_runtime.h>
#include <cuda_bf16.h>
#include <math.h>
#include <stdint.h>

typedef unsigned int u32;

#define Bc   4
#define NQc  2048
#define NKc  2048
#define Dc   1024
#define Hc   8
#define DKc  128
#define DVc  128
#define DOc  1024
#define HBc  32
#define KTILES 16

__device__ float g_qh  [(size_t)Bc*NQc*Hc*DKc];
__device__ float g_kh  [(size_t)Bc*NKc*DKc];
__device__ float g_vh  [(size_t)Bc*NKc*DVc];
__device__ float g_vT  [(size_t)Bc*DVc*NKc];
__device__ float g_outh[(size_t)Bc*NQc*Hc*DVc];

// ---------------- helpers ---------------------------------------------------
__device__ __forceinline__ u32 s2u(const void* p){
    u32 a; asm("{ .reg .u64 t; cvta.to.shared.u64 t, %1; cvt.u32.u64 %0, t; }"
               : "=r"(a) : "l"(p)); return a;
}
__device__ __forceinline__ u32 pkbf2(float a, float b){
    u32 ra = (u32)__bfloat16_as_ushort(__float2bfloat16(a));
    u32 rb = (u32)__bfloat16_as_ushort(__float2bfloat16(b));
    return ra | (rb << 16);
}
__device__ __forceinline__ float bres(float x){
    return x - __bfloat162float(__float2bfloat16(x));
}
__device__ __forceinline__ void ldmx4(u32* r, u32 addr){
    asm volatile("ldmatrix.sync.aligned.m8n8.x4.shared.b16 {%0,%1,%2,%3}, [%4];"
        : "=r"(r[0]), "=r"(r[1]), "=r"(r[2]), "=r"(r[3]) : "r"(addr));
}
__device__ __forceinline__ void mma16816(float* c, const u32* a, u32 b0, u32 b1){
    asm volatile("mma.sync.aligned.m16n8k16.row.col.f32.bf16.bf16.f32 "
        "{%0,%1,%2,%3}, {%4,%5,%6,%7}, {%8,%9}, {%0,%1,%2,%3};"
        : "+f"(c[0]), "+f"(c[1]), "+f"(c[2]), "+f"(c[3])
        : "r"(a[0]), "r"(a[1]), "r"(a[2]), "r"(a[3]), "r"(b0), "r"(b1));
}

// ---- split load/convert: 128 rows x COLS fp32 -> bf16 hi/lo smem -----------
template<int COLS>
__device__ __forceinline__ void loadregs(const float* __restrict__ g, int ldA,
                                         float4* pre, int tid){
    const int PER = (128*COLS/4)/256;
#pragma unroll
    for (int i = 0; i < PER; i++){
        int idx = tid + i*256;
        int row = idx / (COLS/4);
        int c4  = (idx % (COLS/4))*4;
        pre[i] = *(const float4*)(g + (size_t)row*ldA + c4);
    }
}
template<int COLS, int STRIDE>
__device__ __forceinline__ void convert(const float4* pre, char* smHi, char* smLo, int tid){
    const int PER = (128*COLS/4)/256;
#pragma unroll
    for (int i = 0; i < PER; i++){
        int idx = tid + i*256;
        int row = idx / (COLS/4);
        int c4  = (idx % (COLS/4))*4;
        float4 v = pre[i];
        int off = (row*STRIDE + c4)*2;
        *(uint2*)(smHi+off) = make_uint2(pkbf2(v.x,v.y), pkbf2(v.z,v.w));
        *(uint2*)(smLo+off) = make_uint2(pkbf2(bres(v.x),bres(v.y)),
                                         pkbf2(bres(v.z),bres(v.w)));
    }
}
template<int COLS, int STRIDE>
__device__ __forceinline__ void ldconv(const float* __restrict__ g, int ldA,
                                       char* smHi, char* smLo, int tid){
    const int PER = (128*COLS/4)/256;
#pragma unroll
    for (int i = 0; i < PER; i++){
        int idx = tid + i*256;
        int row = idx / (COLS/4);
        int c4  = (idx % (COLS/4))*4;
        float4 v = *(const float4*)(g + (size_t)row*ldA + c4);
        int off = (row*STRIDE + c4)*2;
        *(uint2*)(smHi+off) = make_uint2(pkbf2(v.x,v.y), pkbf2(v.z,v.w));
        *(uint2*)(smLo+off) = make_uint2(pkbf2(bres(v.x),bres(v.y)),
                                         pkbf2(bres(v.z),bres(v.w)));
    }
}

// One k-step (k=16): warp computes 32x64 using split bf16x3.
template<int SA, int SB>
__device__ __forceinline__ void wstep(u32 Ah, u32 Al, u32 Bh, u32 Bl,
                                      int ks, int warp_m, int warp_n, int lane,
                                      float c[2][8][4]){
    const int rsel = lane & 15, ksel = (lane >> 4) << 3;
    const int kb = ks*16 + ksel;
    u32 ah[2][4], al[2][4], bh[4][4], bl[4][4];
#pragma unroll
    for (int mt = 0; mt < 2; mt++){
        u32 off = (u32)((warp_m*32 + mt*16 + rsel)*SA + kb)*2;
        ldmx4(ah[mt], Ah + off);
        ldmx4(al[mt], Al + off);
    }
#pragma unroll
    for (int p = 0; p < 4; p++){
        u32 off = (u32)((warp_n*64 + p*16 + rsel)*SB + kb)*2;
        ldmx4(bh[p], Bh + off);
        ldmx4(bl[p], Bl + off);
    }
#pragma unroll
    for (int mt = 0; mt < 2; mt++)
#pragma unroll
        for (int nt = 0; nt < 8; nt++){
            int p = nt >> 1, s = nt & 1;
            u32 b0h = bh[p][s], b1h = bh[p][2+s];
            u32 b0l = bl[p][s], b1l = bl[p][2+s];
            mma16816(c[mt][nt], ah[mt], b0h, b1h);
            mma16816(c[mt][nt], ah[mt], b0l, b1l);
            mma16816(c[mt][nt], al[mt], b0h, b1h);
        }
}

// ---------------------------------------------------------------------------
// proj: C[M,N] = A[M,K] @ W[N,K]^T + bias (register-prefetched).
// ---------------------------------------------------------------------------
#define PSTR 72
#define PTILE (128*PSTR*2)
__global__ void __launch_bounds__(256) proj_mma(
    const float* __restrict__ A, const float* __restrict__ W,
    const float* __restrict__ bias, float* __restrict__ C,
    int M, int N, int K)
{
    extern __shared__ char sm[];
    u32 sb = s2u(sm);
    const int tid = threadIdx.x, lane = tid & 31, wid = tid >> 5;
    const int warp_m = wid & 3, warp_n = wid >> 2;
    const int n0 = blockIdx.x << 7, m0 = blockIdx.y << 7;

    char* Ahp = sm;            char* Alp = sm + PTILE;
    char* Bhp = sm + 2*PTILE;  char* Blp = sm + 3*PTILE;
    const u32 Ah = sb, Al = sb + PTILE, Bh = sb + 2*PTILE, Bl = sb + 3*PTILE;

    float c[2][8][4];
#pragma unroll
    for (int i=0;i<2;i++) for (int j=0;j<8;j++) for (int q=0;q<4;q++) c[i][j][q]=0.f;

    float4 preA[8], preW[8];
    loadregs<64>(A + (size_t)m0*K, K, preA, tid);
    loadregs<64>(W + (size_t)n0*K, K, preW, tid);

    const int NC = K/64;
    for (int kc = 0; kc < NC; kc++){
        convert<64,PSTR>(preA, Ahp, Alp, tid);
        convert<64,PSTR>(preW, Bhp, Blp, tid);
        __syncthreads();
        if (kc + 1 < NC){
            loadregs<64>(A + (size_t)m0*K + (kc+1)*64, K, preA, tid);
            loadregs<64>(W + (size_t)n0*K + (kc+1)*64, K, preW, tid);
        }
#pragma unroll
        for (int ks = 0; ks < 4; ks++)
            wstep<PSTR,PSTR>(Ah, Al, Bh, Bl, ks, warp_m, warp_n, lane, c);
        __syncthreads();
    }

#pragma unroll
    for (int mt = 0; mt < 2; mt++)
#pragma unroll
        for (int rh = 0; rh < 2; rh++){
            int row = m0 + warp_m*32 + mt*16 + rh*8 + (lane >> 2);
#pragma unroll
            for (int nt = 0; nt < 8; nt++){
                int col = n0 + warp_n*64 + nt*8 + ((lane & 3) << 1);
                float2 o;
                o.x = c[mt][nt][rh*2+0] + __ldg(bias + col);
                o.y = c[mt][nt][rh*2+1] + __ldg(bias + col + 1);
                *(float2*)(C + (size_t)row*N + col) = o;
            }
        }
}

// vh [b,k,d] -> vT [b,d,k]
__global__ void transpose_v(const float* __restrict__ vh, float* __restrict__ vT){
    __shared__ float t[32][33];
    int b = blockIdx.z;
    int k0 = blockIdx.x*32, d0 = blockIdx.y*32;
    int x = threadIdx.x, y = threadIdx.y;
#pragma unroll
    for (int i = 0; i < 32; i += 8)
        t[y+i][x] = vh[(size_t)(b*NKc + k0 + y + i)*DVc + d0 + x];
    __syncthreads();
#pragma unroll
    for (int i = 0; i < 32; i += 8)
        vT[((size_t)b*DVc + d0 + y + i)*NKc + k0 + x] = t[x][y+i];
}

// ---------------------------------------------------------------------------
// fused attention, low-exp softmax:
//  Phase 1: per k-tile, local max first (no exp), write p~ = exp(s-mloc)
//           to attn, track (m, l) running stats (2 exps/tile).
//  Combine -> Ms, Li; convert mloc -> factor f = exp(mloc - M)/L (in smem).
//  Phase 2: P = p~ * f (pure MUL), accumulate P@V.
// ---------------------------------------------------------------------------
#define SSTR 136
#define STILE (128*SSTR*2)
__global__ void __launch_bounds__(256) fused_attn(
    const float* __restrict__ qh, const float* __restrict__ kh,
    const float* __restrict__ vT, const float* __restrict__ mask,
    float* __restrict__ attn, float* __restrict__ outh)
{
    extern __shared__ char sm[];
    __shared__ float Ms[128], Li[128];
    __shared__ float sM2[2][128], sL2[2][128];
    __shared__ float sMloc[KTILES][2][128];   // tile-local max -> later factor
    u32 sb = s2u(sm);
    const int tid = threadIdx.x, lane = tid & 31, wid = tid >> 5;
    const int warp_m = wid & 3, warp_n = wid >> 2;
    const int q0 = blockIdx.x << 7;
    const int hb = blockIdx.y, b = hb >> 3, h = hb & 7;

    char* Ahp = sm;            char* Alp = sm + STILE;   // Q, later P
    char* Bhp = sm + 2*STILE;  char* Blp = sm + 3*STILE; // K, later V
    const u32 Ah = sb, Al = sb + STILE, Bh = sb + 2*STILE, Bl = sb + 3*STILE;

    const float* qbase = qh + (size_t)(b*NQc + q0)*Dc + h*DKc;
    const float* kbase = kh + (size_t)b*NKc*DKc;
    const float* vbase = vT + (size_t)b*DVc*NKc;
    float* abase = attn + ((size_t)(h*Bc + b)*NQc + q0)*NKc;

    // ---- Phase 1: scores, p~ = exp(s - mloc) ----
    ldconv<128,SSTR>(qbase, Dc, Ahp, Alp, tid);

    float4 preK[16];
    loadregs<128>(kbase, DKc, preK, tid);

    const float scale = 0.08838834764831845f;
    float rm_[2][2], rl_[2][2];
#pragma unroll
    for (int i=0;i<2;i++)
#pragma unroll
        for (int j=0;j<2;j++){ rm_[i][j] = -1e30f; rl_[i][j] = 0.f; }

    for (int kt = 0; kt < KTILES; kt++){
        convert<128,SSTR>(preK, Bhp, Blp, tid);
        __syncthreads();
        if (kt + 1 < KTILES)
            loadregs<128>(kbase + (size_t)((kt+1)*128)*DKc, DKc, preK, tid);

        float c[2][8][4];
#pragma unroll
        for (int i=0;i<2;i++) for (int j=0;j<8;j++) for (int q=0;q<4;q++) c[i][j][q]=0.f;
#pragma unroll
        for (int ks = 0; ks < 8; ks++)
            wstep<SSTR,SSTR>(Ah, Al, Bh, Bl, ks, warp_m, warp_n, lane, c);

#pragma unroll
        for (int mt = 0; mt < 2; mt++)
#pragma unroll
            for (int rh = 0; rh < 2; rh++){
                int rowl = warp_m*32 + mt*16 + rh*8 + (lane >> 2);
                const float* mrow = mask + ((size_t)b*NQc + q0 + rowl)*NKc + kt*128;
                float* arow = abase + (size_t)rowl*NKc + kt*128;
                // pass A: scores into registers, find local max (no exp)
                float sv[16];
                float mloc = -1e30f;
#pragma unroll
                for (int nt = 0; nt < 8; nt++){
                    int col = warp_n*64 + nt*8 + ((lane & 3) << 1);
                    float2 mv = *(const float2*)(mrow + col);
                    sv[2*nt+0] = fmaf(c[mt][nt][rh*2+0], scale, mv.x);
                    sv[2*nt+1] = fmaf(c[mt][nt][rh*2+1], scale, mv.y);
                    mloc = fmaxf(mloc, fmaxf(sv[2*nt+0], sv[2*nt+1]));
                }
#pragma unroll
                for (int off = 1; off <= 2; off <<= 1)
                    mloc = fmaxf(mloc, __shfl_xor_sync(0xFFFFFFFFu, mloc, off));
                // pass B: one exp per element, write p~, accumulate tile sum
                float let = 0.f;
#pragma unroll
                for (int nt = 0; nt < 8; nt++){
                    int col = warp_n*64 + nt*8 + ((lane & 3) << 1);
                    float p0 = __expf(sv[2*nt+0] - mloc);
                    float p1 = __expf(sv[2*nt+1] - mloc);
                    *(float2*)(arow + col) = make_float2(p0, p1);
                    let += p0 + p1;
                }
#pragma unroll
                for (int off = 1; off <= 2; off <<= 1)
                    let += __shfl_xor_sync(0xFFFFFFFFu, let, off);
                // merge into running stats (quad-uniform)
                float mx = rm_[mt][rh], le = rl_[mt][rh];
                float nm = fmaxf(mx, mloc);
                le = le*__expf(mx - nm) + let*__expf(mloc - nm);
                rm_[mt][rh] = nm; rl_[mt][rh] = le;
                if ((lane & 3) == 0)
                    sMloc[kt][warp_n][rowl] = mloc;
            }
        __syncthreads();
    }

    // ---- stat combine across warp_n halves (stats already quad-uniform) ----
#pragma unroll
    for (int mt = 0; mt < 2; mt++)
#pragma unroll
        for (int rh = 0; rh < 2; rh++){
            int rowl = warp_m*32 + mt*16 + rh*8 + (lane >> 2);
            if ((lane & 3) == 0){
                sM2[warp_n][rowl] = rm_[mt][rh];
                sL2[warp_n][rowl] = rl_[mt][rh];
            }
        }
    __syncthreads();
    if (tid < 128){
        float m0 = sM2[0][tid], m1 = sM2[1][tid];
        float M = fmaxf(m0, m1);
        float L = sL2[0][tid]*__expf(m0 - M) + sL2[1][tid]*__expf(m1 - M);
        Ms[tid] = M; Li[tid] = 1.0f / L;
    }
    __syncthreads();
    // convert sMloc -> factor f = exp(mloc - M)/L  (in place; 4096 exps)
    for (int i = tid; i < KTILES*2*128; i += 256){
        int kt = i >> 8, half = (i >> 7) & 1, row = i & 127;
        sMloc[kt][half][row] = __expf(sMloc[kt][half][row] - Ms[row]) * Li[row];
    }
    __syncthreads();

    // ---- Phase 2: P = p~ * f, accumulate P@V ----
    float4 preP[16];
    loadregs<128>(abase, NKc, preP, tid);

    float c[2][8][4];
#pragma unroll
    for (int i=0;i<2;i++) for (int j=0;j<8;j++) for (int q=0;q<4;q++) c[i][j][q]=0.f;

    for (int kt = 0; kt < KTILES; kt++){
#pragma unroll
        for (int i = 0; i < 16; i++){
            int idx = tid + i*256;
            int row = idx >> 5, c4 = (idx & 31) << 2;
            float4 s = preP[i];
            float f = sMloc[kt][c4 >> 6][row];
            float4 p;
            p.x = s.x * f; p.y = s.y * f; p.z = s.z * f; p.w = s.w * f;
            *(float4*)(abase + (size_t)row*NKc + kt*128 + c4) = p;
            int off = (row*SSTR + c4)*2;
            *(uint2*)(Ahp+off) = make_uint2(pkbf2(p.x,p.y), pkbf2(p.z,p.w));
            *(uint2*)(Alp+off) = make_uint2(pkbf2(bres(p.x),bres(p.y)),
                                            pkbf2(bres(p.z),bres(p.w)));
        }
        ldconv<128,SSTR>(vbase + kt*128, NKc, Bhp, Blp, tid);
        __syncthreads();
        if (kt + 1 < KTILES)
            loadregs<128>(abase + (kt+1)*128, NKc, preP, tid);
#pragma unroll
        for (int ks = 0; ks < 8; ks++)
            wstep<SSTR,SSTR>(Ah, Al, Bh, Bl, ks, warp_m, warp_n, lane, c);
        __syncthreads();
    }

#pragma unroll
    for (int mt = 0; mt < 2; mt++)
#pragma unroll
        for (int rh = 0; rh < 2; rh++){
            int row = q0 + warp_m*32 + mt*16 + rh*8 + (lane >> 2);
            float* op = outh + (size_t)(b*NQc + row)*(Hc*DVc) + h*DVc;
#pragma unroll
            for (int nt = 0; nt < 8; nt++){
                int col = warp_n*64 + nt*8 + ((lane & 3) << 1);
                *(float2*)(op + col) = make_float2(c[mt][nt][rh*2+0], c[mt][nt][rh*2+1]);
            }
        }
}

// ---------------------------------------------------------------------------
extern "C" void kernel_launch(void* const* d_in, const int* in_sizes, int n_in,
                              void* d_out, int out_size)
{
    const float* q    = (const float*)d_in[0];
    const float* k    = (const float*)d_in[1];
    const float* v    = (const float*)d_in[2];
    const float* mask = (const float*)d_in[3];
    const float* Wq   = (const float*)d_in[4];
    const float* bq   = (const float*)d_in[5];
    const float* Wk   = (const float*)d_in[6];
    const float* bk   = (const float*)d_in[7];
    const float* Wv   = (const float*)d_in[8];
    const float* bv   = (const float*)d_in[9];
    const float* Wo   = (const float*)d_in[10];
    const float* bo   = (const float*)d_in[11];

    float* attn = (float*)d_out;
    float* outp = attn + (size_t)HBc*NQc*NKc;

    float *qh,*kh,*vh,*vT,*outh;
    cudaGetSymbolAddress((void**)&qh,   g_qh);
    cudaGetSymbolAddress((void**)&kh,   g_kh);
    cudaGetSymbolAddress((void**)&vh,   g_vh);
    cudaGetSymbolAddress((void**)&vT,   g_vT);
    cudaGetSymbolAddress((void**)&outh, g_outh);

    const int PROJ_SM = 4*PTILE;           // 73728
    const int FUS_SM  = 4*STILE;           // 139264
    cudaFuncSetAttribute(proj_mma,   cudaFuncAttributeMaxDynamicSharedMemorySize, PROJ_SM);
    cudaFuncSetAttribute(fused_attn, cudaFuncAttributeMaxDynamicSharedMemorySize, FUS_SM);

    dim3 blk(256);
    const int Mr = Bc*NQc;   // 8192

    proj_mma<<<dim3((Hc*DKc)/128, Mr/128), blk, PROJ_SM>>>(q, Wq, bq, qh, Mr, Hc*DKc, Dc);
    proj_mma<<<dim3(1,            Mr/128), blk, PROJ_SM>>>(k, Wk, bk, kh, Mr, DKc, Dc);
    proj_mma<<<dim3(1,            Mr/128), blk, PROJ_SM>>>(v, Wv, bv, vh, Mr, DVc, Dc);

    transpose_v<<<dim3(NKc/32, DVc/32, Bc), dim3(32,8)>>>(vh, vT);

    fused_attn<<<dim3(NQc/128, HBc), blk, FUS_SM>>>(qh, kh, vT, mask, attn, outh);

    proj_mma<<<dim3(DOc/128, Mr/128), blk, PROJ_SM>>>(outh, Wo, bo, outp, Mr, DOc, Hc*DVc);
}

// round 12
// speedup vs baseline: 1.5194x; 1.0604x over previous
#include <cuda_runtime.h>
#include <cuda_bf16.h>
#include <math.h>
#include <stdint.h>

typedef unsigned int u32;

#define Bc   4
#define NQc  2048
#define NKc  2048
#define Dc   1024
#define Hc   8
#define DKc  128
#define DVc  128
#define DOc  1024
#define HBc  32
#define KTILES 16

__device__ float g_qh  [(size_t)Bc*NQc*Hc*DKc];
__device__ float g_kh  [(size_t)Bc*NKc*DKc];
__device__ float g_vh  [(size_t)Bc*NKc*DVc];
__device__ float g_vT  [(size_t)Bc*DVc*NKc];
__device__ float g_outh[(size_t)Bc*NQc*Hc*DVc];

// ---------------- helpers ---------------------------------------------------
__device__ __forceinline__ u32 s2u(const void* p){
    u32 a; asm("{ .reg .u64 t; cvta.to.shared.u64 t, %1; cvt.u32.u64 %0, t; }"
               : "=r"(a) : "l"(p)); return a;
}
__device__ __forceinline__ u32 pkbf2(float a, float b){
    u32 ra = (u32)__bfloat16_as_ushort(__float2bfloat16(a));
    u32 rb = (u32)__bfloat16_as_ushort(__float2bfloat16(b));
    return ra | (rb << 16);
}
__device__ __forceinline__ float bres(float x){
    return x - __bfloat162float(__float2bfloat16(x));
}
__device__ __forceinline__ void ldmx4(u32* r, u32 addr){
    asm volatile("ldmatrix.sync.aligned.m8n8.x4.shared.b16 {%0,%1,%2,%3}, [%4];"
        : "=r"(r[0]), "=r"(r[1]), "=r"(r[2]), "=r"(r[3]) : "r"(addr));
}
__device__ __forceinline__ void mma16816(float* c, const u32* a, u32 b0, u32 b1){
    asm volatile("mma.sync.aligned.m16n8k16.row.col.f32.bf16.bf16.f32 "
        "{%0,%1,%2,%3}, {%4,%5,%6,%7}, {%8,%9}, {%0,%1,%2,%3};"
        : "+f"(c[0]), "+f"(c[1]), "+f"(c[2]), "+f"(c[3])
        : "r"(a[0]), "r"(a[1]), "r"(a[2]), "r"(a[3]), "r"(b0), "r"(b1));
}

// 128-row helpers (projection path, register-prefetched)
template<int COLS>
__device__ __forceinline__ void loadregs(const float* __restrict__ g, int ldA,
                                         float4* pre, int tid){
    const int PER = (128*COLS/4)/256;
#pragma unroll
    for (int i = 0; i < PER; i++){
        int idx = tid + i*256;
        int row = idx / (COLS/4);
        int c4  = (idx % (COLS/4))*4;
        pre[i] = *(const float4*)(g + (size_t)row*ldA + c4);
    }
}
template<int COLS, int STRIDE>
__device__ __forceinline__ void convert(const float4* pre, char* smHi, char* smLo, int tid){
    const int PER = (128*COLS/4)/256;
#pragma unroll
    for (int i = 0; i < PER; i++){
        int idx = tid + i*256;
        int row = idx / (COLS/4);
        int c4  = (idx % (COLS/4))*4;
        float4 v = pre[i];
        int off = (row*STRIDE + c4)*2;
        *(uint2*)(smHi+off) = make_uint2(pkbf2(v.x,v.y), pkbf2(v.z,v.w));
        *(uint2*)(smLo+off) = make_uint2(pkbf2(bres(v.x),bres(v.y)),
                                         pkbf2(bres(v.z),bres(v.w)));
    }
}
// generic rows x 128 direct ldconv
template<int ROWS, int STRIDE>
__device__ __forceinline__ void ldconvR(const float* __restrict__ g, int ldA,
                                        char* smHi, char* smLo, int tid){
    const int PER = (ROWS*32)/256;
#pragma unroll
    for (int i = 0; i < PER; i++){
        int idx = tid + i*256;
        int row = idx >> 5;
        int c4  = (idx & 31) << 2;
        float4 v = *(const float4*)(g + (size_t)row*ldA + c4);
        int off = (row*STRIDE + c4)*2;
        *(uint2*)(smHi+off) = make_uint2(pkbf2(v.x,v.y), pkbf2(v.z,v.w));
        *(uint2*)(smLo+off) = make_uint2(pkbf2(bres(v.x),bres(v.y)),
                                         pkbf2(bres(v.z),bres(v.w)));
    }
}

// 128x128-output warp step (proj): warp computes 32x64
template<int SA, int SB>
__device__ __forceinline__ void wstep(u32 Ah, u32 Al, u32 Bh, u32 Bl,
                                      int ks, int warp_m, int warp_n, int lane,
                                      float c[2][8][4]){
    const int rsel = lane & 15, ksel = (lane >> 4) << 3;
    const int kb = ks*16 + ksel;
    u32 ah[2][4], al[2][4], bh[4][4], bl[4][4];
#pragma unroll
    for (int mt = 0; mt < 2; mt++){
        u32 off = (u32)((warp_m*32 + mt*16 + rsel)*SA + kb)*2;
        ldmx4(ah[mt], Ah + off);
        ldmx4(al[mt], Al + off);
    }
#pragma unroll
    for (int p = 0; p < 4; p++){
        u32 off = (u32)((warp_n*64 + p*16 + rsel)*SB + kb)*2;
        ldmx4(bh[p], Bh + off);
        ldmx4(bl[p], Bl + off);
    }
#pragma unroll
    for (int mt = 0; mt < 2; mt++)
#pragma unroll
        for (int nt = 0; nt < 8; nt++){
            int p = nt >> 1, s = nt & 1;
            mma16816(c[mt][nt], ah[mt], bh[p][s], bh[p][2+s]);
            mma16816(c[mt][nt], ah[mt], bl[p][s], bl[p][2+s]);
            mma16816(c[mt][nt], al[mt], bh[p][s], bh[p][2+s]);
        }
}

// 64x128-output warp step (fused): warp computes 16x64
template<int SA, int SB>
__device__ __forceinline__ void wstep64(u32 Ah, u32 Al, u32 Bh, u32 Bl,
                                        int ks, int warp_m, int warp_n, int lane,
                                        float c[8][4]){
    const int rsel = lane & 15, ksel = (lane >> 4) << 3;
    const int kb = ks*16 + ksel;
    u32 ah[4], al[4], bh[4][4], bl[4][4];
    {
        u32 off = (u32)((warp_m*16 + rsel)*SA + kb)*2;
        ldmx4(ah, Ah + off);
        ldmx4(al, Al + off);
    }
#pragma unroll
    for (int p = 0; p < 4; p++){
        u32 off = (u32)((warp_n*64 + p*16 + rsel)*SB + kb)*2;
        ldmx4(bh[p], Bh + off);
        ldmx4(bl[p], Bl + off);
    }
#pragma unroll
    for (int nt = 0; nt < 8; nt++){
        int p = nt >> 1, s = nt & 1;
        mma16816(c[nt], ah, bh[p][s], bh[p][2+s]);
        mma16816(c[nt], ah, bl[p][s], bl[p][2+s]);
        mma16816(c[nt], al, bh[p][s], bh[p][2+s]);
    }
}

// ---------------------------------------------------------------------------
// proj: C[M,N] = A[M,K] @ W[N,K]^T + bias (R7 form, unchanged).
// ---------------------------------------------------------------------------
#define PSTR 72
#define PTILE (128*PSTR*2)
__global__ void __launch_bounds__(256) proj_mma(
    const float* __restrict__ A, const float* __restrict__ W,
    const float* __restrict__ bias, float* __restrict__ C,
    int M, int N, int K)
{
    extern __shared__ char sm[];
    u32 sb = s2u(sm);
    const int tid = threadIdx.x, lane = tid & 31, wid = tid >> 5;
    const int warp_m = wid & 3, warp_n = wid >> 2;
    const int n0 = blockIdx.x << 7, m0 = blockIdx.y << 7;

    char* Ahp = sm;            char* Alp = sm + PTILE;
    char* Bhp = sm + 2*PTILE;  char* Blp = sm + 3*PTILE;
    const u32 Ah = sb, Al = sb + PTILE, Bh = sb + 2*PTILE, Bl = sb + 3*PTILE;

    float c[2][8][4];
#pragma unroll
    for (int i=0;i<2;i++) for (int j=0;j<8;j++) for (int q=0;q<4;q++) c[i][j][q]=0.f;

    float4 preA[8], preW[8];
    loadregs<64>(A + (size_t)m0*K, K, preA, tid);
    loadregs<64>(W + (size_t)n0*K, K, preW, tid);

    const int NC = K/64;
    for (int kc = 0; kc < NC; kc++){
        convert<64,PSTR>(preA, Ahp, Alp, tid);
        convert<64,PSTR>(preW, Bhp, Blp, tid);
        __syncthreads();
        if (kc + 1 < NC){
            loadregs<64>(A + (size_t)m0*K + (kc+1)*64, K, preA, tid);
            loadregs<64>(W + (size_t)n0*K + (kc+1)*64, K, preW, tid);
        }
#pragma unroll
        for (int ks = 0; ks < 4; ks++)
            wstep<PSTR,PSTR>(Ah, Al, Bh, Bl, ks, warp_m, warp_n, lane, c);
        __syncthreads();
    }

#pragma unroll
    for (int mt = 0; mt < 2; mt++)
#pragma unroll
        for (int rh = 0; rh < 2; rh++){
            int row = m0 + warp_m*32 + mt*16 + rh*8 + (lane >> 2);
#pragma unroll
            for (int nt = 0; nt < 8; nt++){
                int col = n0 + warp_n*64 + nt*8 + ((lane & 3) << 1);
                float2 o;
                o.x = c[mt][nt][rh*2+0] + __ldg(bias + col);
                o.y = c[mt][nt][rh*2+1] + __ldg(bias + col + 1);
                *(float2*)(C + (size_t)row*N + col) = o;
            }
        }
}

// vh [b,k,d] -> vT [b,d,k]
__global__ void transpose_v(const float* __restrict__ vh, float* __restrict__ vT){
    __shared__ float t[32][33];
    int b = blockIdx.z;
    int k0 = blockIdx.x*32, d0 = blockIdx.y*32;
    int x = threadIdx.x, y = threadIdx.y;
#pragma unroll
    for (int i = 0; i < 32; i += 8)
        t[y+i][x] = vh[(size_t)(b*NKc + k0 + y + i)*DVc + d0 + x];
    __syncthreads();
#pragma unroll
    for (int i = 0; i < 32; i += 8)
        vT[((size_t)b*DVc + d0 + y + i)*NKc + k0 + x] = t[x][y+i];
}

// ---------------------------------------------------------------------------
// fused attention, 64-row q-tiles, 2 CTAs/SM:
//  Phase 1: 16 k-tiles raw S = scale*(Q@K^T)+mask -> attn; per-tile 2-pass
//           stats (max first, then 1 exp/elem for tile sum), running (m,l).
//  Combine -> Ms, Li.
//  Phase 2: P = exp(s - M)*Li, write back, accumulate P@V.
// ---------------------------------------------------------------------------
#define SSTR 136
#define QTILE (64*SSTR*2)    // 17408
#define KTILE (128*SSTR*2)   // 34816
#define FUS_SM (2*QTILE + 2*KTILE)  // 104448
__global__ void __launch_bounds__(256,2) fused_attn(
    const float* __restrict__ qh, const float* __restrict__ kh,
    const float* __restrict__ vT, const float* __restrict__ mask,
    float* __restrict__ attn, float* __restrict__ outh)
{
    extern __shared__ char sm[];
    __shared__ float Ms[64], Li[64];
    __shared__ float sM2[2][64], sL2[2][64];
    u32 sb = s2u(sm);
    const int tid = threadIdx.x, lane = tid & 31, wid = tid >> 5;
    const int warp_m = wid & 3, warp_n = wid >> 2;   // 4 x 16 rows, 2 x 64 cols
    const int q0 = blockIdx.x << 6;
    const int hb = blockIdx.y, b = hb >> 3, h = hb & 7;

    char* Ahp = sm;                    char* Alp = sm + QTILE;          // Q, later P
    char* Bhp = sm + 2*QTILE;          char* Blp = sm + 2*QTILE + KTILE; // K, later V
    const u32 Ah = sb, Al = sb + QTILE, Bh = sb + 2*QTILE, Bl = sb + 2*QTILE + KTILE;

    const float* qbase = qh + (size_t)(b*NQc + q0)*Dc + h*DKc;
    const float* kbase = kh + (size_t)b*NKc*DKc;
    const float* vbase = vT + (size_t)b*DVc*NKc;
    float* abase = attn + ((size_t)(h*Bc + b)*NQc + q0)*NKc;

    // ---- Phase 1 ----
    ldconvR<64,SSTR>(qbase, Dc, Ahp, Alp, tid);

    const float scale = 0.08838834764831845f;
    float rm_[2] = {-1e30f, -1e30f}, rl_[2] = {0.f, 0.f};

    for (int kt = 0; kt < KTILES; kt++){
        ldconvR<128,SSTR>(kbase + (size_t)(kt*128)*DKc, DKc, Bhp, Blp, tid);
        __syncthreads();

        float c[8][4];
#pragma unroll
        for (int j=0;j<8;j++) for (int q=0;q<4;q++) c[j][q]=0.f;
#pragma unroll
        for (int ks = 0; ks < 8; ks++)
            wstep64<SSTR,SSTR>(Ah, Al, Bh, Bl, ks, warp_m, warp_n, lane, c);

#pragma unroll
        for (int rh = 0; rh < 2; rh++){
            int rowl = warp_m*16 + rh*8 + (lane >> 2);
            const float* mrow = mask + ((size_t)b*NQc + q0 + rowl)*NKc + kt*128;
            float* arow = abase + (size_t)rowl*NKc + kt*128;
            float sv[16];
            float mloc = -1e30f;
#pragma unroll
            for (int nt = 0; nt < 8; nt++){
                int col = warp_n*64 + nt*8 + ((lane & 3) << 1);
                float2 mv = *(const float2*)(mrow + col);
                sv[2*nt+0] = fmaf(c[nt][rh*2+0], scale, mv.x);
                sv[2*nt+1] = fmaf(c[nt][rh*2+1], scale, mv.y);
                *(float2*)(arow + col) = make_float2(sv[2*nt+0], sv[2*nt+1]);
                mloc = fmaxf(mloc, fmaxf(sv[2*nt+0], sv[2*nt+1]));
            }
#pragma unroll
            for (int off = 1; off <= 2; off <<= 1)
                mloc = fmaxf(mloc, __shfl_xor_sync(0xFFFFFFFFu, mloc, off));
            float let = 0.f;
#pragma unroll
            for (int nt = 0; nt < 8; nt++){
                let += __expf(sv[2*nt+0] - mloc);
                let += __expf(sv[2*nt+1] - mloc);
            }
#pragma unroll
            for (int off = 1; off <= 2; off <<= 1)
                let += __shfl_xor_sync(0xFFFFFFFFu, let, off);
            float nm = fmaxf(rm_[rh], mloc);
            rl_[rh] = rl_[rh]*__expf(rm_[rh] - nm) + let*__expf(mloc - nm);
            rm_[rh] = nm;
        }
        __syncthreads();
    }

    // ---- stat combine ----
#pragma unroll
    for (int rh = 0; rh < 2; rh++){
        int rowl = warp_m*16 + rh*8 + (lane >> 2);
        if ((lane & 3) == 0){
            sM2[warp_n][rowl] = rm_[rh];
            sL2[warp_n][rowl] = rl_[rh];
        }
    }
    __syncthreads();
    if (tid < 64){
        float m0 = sM2[0][tid], m1 = sM2[1][tid];
        float M = fmaxf(m0, m1);
        float L = sL2[0][tid]*__expf(m0 - M) + sL2[1][tid]*__expf(m1 - M);
        Ms[tid] = M; Li[tid] = 1.0f / L;
    }
    __syncthreads();

    // ---- Phase 2: P = exp(s - M)*Li, accumulate P@V ----
    float c[8][4];
#pragma unroll
    for (int j=0;j<8;j++) for (int q=0;q<4;q++) c[j][q]=0.f;

    for (int kt = 0; kt < KTILES; kt++){
#pragma unroll
        for (int i = 0; i < 8; i++){       // 64*32/256 = 8 float4 per thread
            int idx = tid + i*256;
            int row = idx >> 5, c4 = (idx & 31) << 2;
            float* ap = abase + (size_t)row*NKc + kt*128 + c4;
            float4 s = *(float4*)ap;
            float mm = Ms[row], li = Li[row];
            float4 p;
            p.x = __expf(s.x - mm)*li; p.y = __expf(s.y - mm)*li;
            p.z = __expf(s.z - mm)*li; p.w = __expf(s.w - mm)*li;
            *(float4*)ap = p;
            int off = (row*SSTR + c4)*2;
            *(uint2*)(Ahp+off) = make_uint2(pkbf2(p.x,p.y), pkbf2(p.z,p.w));
            *(uint2*)(Alp+off) = make_uint2(pkbf2(bres(p.x),bres(p.y)),
                                            pkbf2(bres(p.z),bres(p.w)));
        }
        ldconvR<128,SSTR>(vbase + kt*128, NKc, Bhp, Blp, tid);
        __syncthreads();
#pragma unroll
        for (int ks = 0; ks < 8; ks++)
            wstep64<SSTR,SSTR>(Ah, Al, Bh, Bl, ks, warp_m, warp_n, lane, c);
        __syncthreads();
    }

#pragma unroll
    for (int rh = 0; rh < 2; rh++){
        int row = q0 + warp_m*16 + rh*8 + (lane >> 2);
        float* op = outh + (size_t)(b*NQc + row)*(Hc*DVc) + h*DVc;
#pragma unroll
        for (int nt = 0; nt < 8; nt++){
            int col = warp_n*64 + nt*8 + ((lane & 3) << 1);
            *(float2*)(op + col) = make_float2(c[nt][rh*2+0], c[nt][rh*2+1]);
        }
    }
}

// ---------------------------------------------------------------------------
extern "C" void kernel_launch(void* const* d_in, const int* in_sizes, int n_in,
                              void* d_out, int out_size)
{
    const float* q    = (const float*)d_in[0];
    const float* k    = (const float*)d_in[1];
    const float* v    = (const float*)d_in[2];
    const float* mask = (const float*)d_in[3];
    const float* Wq   = (const float*)d_in[4];
    const float* bq   = (const float*)d_in[5];
    const float* Wk   = (const float*)d_in[6];
    const float* bk   = (const float*)d_in[7];
    const float* Wv   = (const float*)d_in[8];
    const float* bv   = (const float*)d_in[9];
    const float* Wo   = (const float*)d_in[10];
    const float* bo   = (const float*)d_in[11];

    float* attn = (float*)d_out;
    float* outp = attn + (size_t)HBc*NQc*NKc;

    float *qh,*kh,*vh,*vT,*outh;
    cudaGetSymbolAddress((void**)&qh,   g_qh);
    cudaGetSymbolAddress((void**)&kh,   g_kh);
    cudaGetSymbolAddress((void**)&vh,   g_vh);
    cudaGetSymbolAddress((void**)&vT,   g_vT);
    cudaGetSymbolAddress((void**)&outh, g_outh);

    const int PROJ_SM = 4*PTILE;           // 73728
    cudaFuncSetAttribute(proj_mma,   cudaFuncAttributeMaxDynamicSharedMemorySize, PROJ_SM);
    cudaFuncSetAttribute(fused_attn, cudaFuncAttributeMaxDynamicSharedMemorySize, FUS_SM);

    dim3 blk(256);
    const int Mr = Bc*NQc;   // 8192

    proj_mma<<<dim3((Hc*DKc)/128, Mr/128), blk, PROJ_SM>>>(q, Wq, bq, qh, Mr, Hc*DKc, Dc);
    proj_mma<<<dim3(1,            Mr/128), blk, PROJ_SM>>>(k, Wk, bk, kh, Mr, DKc, Dc);
    proj_mma<<<dim3(1,            Mr/128), blk, PROJ_SM>>>(v, Wv, bv, vh, Mr, DVc, Dc);

    transpose_v<<<dim3(NKc/32, DVc/32, Bc), dim3(32,8)>>>(vh, vT);

    fused_attn<<<dim3(NQc/64, HBc), blk, FUS_SM>>>(qh, kh, vT, mask, attn, outh);

    proj_mma<<<dim3(DOc/128, Mr/128), blk, PROJ_SM>>>(outh, Wo, bo, outp, Mr, DOc, Hc*DVc);
}

// round 13
// speedup vs baseline: 1.5747x; 1.0364x over previous
#include <cuda_runtime.h>
#include <cuda_bf16.h>
#include <math.h>
#include <stdint.h>

typedef unsigned int u32;

#define Bc   4
#define NQc  2048
#define NKc  2048
#define Dc   1024
#define Hc   8
#define DKc  128
#define DVc  128
#define DOc  1024
#define HBc  32
#define KTILES 16

__device__ float g_qh  [(size_t)Bc*NQc*Hc*DKc];
__device__ float g_kh  [(size_t)Bc*NKc*DKc];
__device__ float g_vh  [(size_t)Bc*NKc*DVc];
__device__ float g_vT  [(size_t)Bc*DVc*NKc];
__device__ float g_outh[(size_t)Bc*NQc*Hc*DVc];

// ---------------- helpers ---------------------------------------------------
__device__ __forceinline__ u32 s2u(const void* p){
    u32 a; asm("{ .reg .u64 t; cvta.to.shared.u64 t, %1; cvt.u32.u64 %0, t; }"
               : "=r"(a) : "l"(p)); return a;
}
__device__ __forceinline__ u32 pkbf2(float a, float b){
    u32 ra = (u32)__bfloat16_as_ushort(__float2bfloat16(a));
    u32 rb = (u32)__bfloat16_as_ushort(__float2bfloat16(b));
    return ra | (rb << 16);
}
__device__ __forceinline__ float bres(float x){
    return x - __bfloat162float(__float2bfloat16(x));
}
__device__ __forceinline__ void ldmx4(u32* r, u32 addr){
    asm volatile("ldmatrix.sync.aligned.m8n8.x4.shared.b16 {%0,%1,%2,%3}, [%4];"
        : "=r"(r[0]), "=r"(r[1]), "=r"(r[2]), "=r"(r[3]) : "r"(addr));
}
__device__ __forceinline__ void mma16816(float* c, const u32* a, u32 b0, u32 b1){
    asm volatile("mma.sync.aligned.m16n8k16.row.col.f32.bf16.bf16.f32 "
        "{%0,%1,%2,%3}, {%4,%5,%6,%7}, {%8,%9}, {%0,%1,%2,%3};"
        : "+f"(c[0]), "+f"(c[1]), "+f"(c[2]), "+f"(c[3])
        : "r"(a[0]), "r"(a[1]), "r"(a[2]), "r"(a[3]), "r"(b0), "r"(b1));
}

// generic rows x COLS fp32 -> bf16 hi/lo smem
template<int ROWS, int COLS, int STRIDE>
__device__ __forceinline__ void ldconvG(const float* __restrict__ g, int ldA,
                                        char* smHi, char* smLo, int tid){
    const int PER = (ROWS*COLS/4)/256;
#pragma unroll
    for (int i = 0; i < PER; i++){
        int idx = tid + i*256;
        int row = idx / (COLS/4);
        int c4  = (idx % (COLS/4))*4;
        float4 v = *(const float4*)(g + (size_t)row*ldA + c4);
        int off = (row*STRIDE + c4)*2;
        *(uint2*)(smHi+off) = make_uint2(pkbf2(v.x,v.y), pkbf2(v.z,v.w));
        *(uint2*)(smLo+off) = make_uint2(pkbf2(bres(v.x),bres(v.y)),
                                         pkbf2(bres(v.z),bres(v.w)));
    }
}

// 128x128-output warp step (proj): warp computes 32x64
template<int SA, int SB>
__device__ __forceinline__ void wstep(u32 Ah, u32 Al, u32 Bh, u32 Bl,
                                      int ks, int warp_m, int warp_n, int lane,
                                      float c[2][8][4]){
    const int rsel = lane & 15, ksel = (lane >> 4) << 3;
    const int kb = ks*16 + ksel;
    u32 ah[2][4], al[2][4], bh[4][4], bl[4][4];
#pragma unroll
    for (int mt = 0; mt < 2; mt++){
        u32 off = (u32)((warp_m*32 + mt*16 + rsel)*SA + kb)*2;
        ldmx4(ah[mt], Ah + off);
        ldmx4(al[mt], Al + off);
    }
#pragma unroll
    for (int p = 0; p < 4; p++){
        u32 off = (u32)((warp_n*64 + p*16 + rsel)*SB + kb)*2;
        ldmx4(bh[p], Bh + off);
        ldmx4(bl[p], Bl + off);
    }
#pragma unroll
    for (int mt = 0; mt < 2; mt++)
#pragma unroll
        for (int nt = 0; nt < 8; nt++){
            int p = nt >> 1, s = nt & 1;
            mma16816(c[mt][nt], ah[mt], bh[p][s], bh[p][2+s]);
            mma16816(c[mt][nt], ah[mt], bl[p][s], bl[p][2+s]);
            mma16816(c[mt][nt], al[mt], bh[p][s], bh[p][2+s]);
        }
}

// 64x128-output warp step (fused): warp computes 16x64
template<int SA, int SB>
__device__ __forceinline__ void wstep64(u32 Ah, u32 Al, u32 Bh, u32 Bl,
                                        int ks, int warp_m, int warp_n, int lane,
                                        float c[8][4]){
    const int rsel = lane & 15, ksel = (lane >> 4) << 3;
    const int kb = ks*16 + ksel;
    u32 ah[4], al[4], bh[4][4], bl[4][4];
    {
        u32 off = (u32)((warp_m*16 + rsel)*SA + kb)*2;
        ldmx4(ah, Ah + off);
        ldmx4(al, Al + off);
    }
#pragma unroll
    for (int p = 0; p < 4; p++){
        u32 off = (u32)((warp_n*64 + p*16 + rsel)*SB + kb)*2;
        ldmx4(bh[p], Bh + off);
        ldmx4(bl[p], Bl + off);
    }
#pragma unroll
    for (int nt = 0; nt < 8; nt++){
        int p = nt >> 1, s = nt & 1;
        mma16816(c[nt], ah, bh[p][s], bh[p][2+s]);
        mma16816(c[nt], ah, bl[p][s], bl[p][2+s]);
        mma16816(c[nt], al, bh[p][s], bh[p][2+s]);
    }
}

// ---------------------------------------------------------------------------
// proj: C[M,N] = A[M,K] @ W[N,K]^T + bias.
// 2 CTAs/SM: no register prefetch; co-resident CTA hides latency.
// ---------------------------------------------------------------------------
#define PSTR 72
#define PTILE (128*PSTR*2)
#define PROJ_SM (4*PTILE)    // 73728 per CTA -> 2 CTAs/SM
__global__ void __launch_bounds__(256,2) proj_mma(
    const float* __restrict__ A, const float* __restrict__ W,
    const float* __restrict__ bias, float* __restrict__ C,
    int M, int N, int K)
{
    extern __shared__ char sm[];
    u32 sb = s2u(sm);
    const int tid = threadIdx.x, lane = tid & 31, wid = tid >> 5;
    const int warp_m = wid & 3, warp_n = wid >> 2;
    const int n0 = blockIdx.x << 7, m0 = blockIdx.y << 7;

    char* Ahp = sm;            char* Alp = sm + PTILE;
    char* Bhp = sm + 2*PTILE;  char* Blp = sm + 3*PTILE;
    const u32 Ah = sb, Al = sb + PTILE, Bh = sb + 2*PTILE, Bl = sb + 3*PTILE;

    float c[2][8][4];
#pragma unroll
    for (int i=0;i<2;i++) for (int j=0;j<8;j++) for (int q=0;q<4;q++) c[i][j][q]=0.f;

    const int NC = K/64;
    for (int kc = 0; kc < NC; kc++){
        ldconvG<128,64,PSTR>(A + (size_t)m0*K + kc*64, K, Ahp, Alp, tid);
        ldconvG<128,64,PSTR>(W + (size_t)n0*K + kc*64, K, Bhp, Blp, tid);
        __syncthreads();
#pragma unroll
        for (int ks = 0; ks < 4; ks++)
            wstep<PSTR,PSTR>(Ah, Al, Bh, Bl, ks, warp_m, warp_n, lane, c);
        __syncthreads();
    }

#pragma unroll
    for (int mt = 0; mt < 2; mt++)
#pragma unroll
        for (int rh = 0; rh < 2; rh++){
            int row = m0 + warp_m*32 + mt*16 + rh*8 + (lane >> 2);
#pragma unroll
            for (int nt = 0; nt < 8; nt++){
                int col = n0 + warp_n*64 + nt*8 + ((lane & 3) << 1);
                float2 o;
                o.x = c[mt][nt][rh*2+0] + __ldg(bias + col);
                o.y = c[mt][nt][rh*2+1] + __ldg(bias + col + 1);
                *(float2*)(C + (size_t)row*N + col) = o;
            }
        }
}

// vh [b,k,d] -> vT [b,d,k]
__global__ void transpose_v(const float* __restrict__ vh, float* __restrict__ vT){
    __shared__ float t[32][33];
    int b = blockIdx.z;
    int k0 = blockIdx.x*32, d0 = blockIdx.y*32;
    int x = threadIdx.x, y = threadIdx.y;
#pragma unroll
    for (int i = 0; i < 32; i += 8)
        t[y+i][x] = vh[(size_t)(b*NKc + k0 + y + i)*DVc + d0 + x];
    __syncthreads();
#pragma unroll
    for (int i = 0; i < 32; i += 8)
        vT[((size_t)b*DVc + d0 + y + i)*NKc + k0 + x] = t[x][y+i];
}

// ---------------------------------------------------------------------------
// fused attention, 64-row q-tiles, 2 CTAs/SM (unchanged from R12).
// ---------------------------------------------------------------------------
#define SSTR 136
#define QTILE (64*SSTR*2)    // 17408
#define KTILE (128*SSTR*2)   // 34816
#define FUS_SM (2*QTILE + 2*KTILE)  // 104448
__global__ void __launch_bounds__(256,2) fused_attn(
    const float* __restrict__ qh, const float* __restrict__ kh,
    const float* __restrict__ vT, const float* __restrict__ mask,
    float* __restrict__ attn, float* __restrict__ outh)
{
    extern __shared__ char sm[];
    __shared__ float Ms[64], Li[64];
    __shared__ float sM2[2][64], sL2[2][64];
    u32 sb = s2u(sm);
    const int tid = threadIdx.x, lane = tid & 31, wid = tid >> 5;
    const int warp_m = wid & 3, warp_n = wid >> 2;
    const int q0 = blockIdx.x << 6;
    const int hb = blockIdx.y, b = hb >> 3, h = hb & 7;

    char* Ahp = sm;                    char* Alp = sm + QTILE;
    char* Bhp = sm + 2*QTILE;          char* Blp = sm + 2*QTILE + KTILE;
    const u32 Ah = sb, Al = sb + QTILE, Bh = sb + 2*QTILE, Bl = sb + 2*QTILE + KTILE;

    const float* qbase = qh + (size_t)(b*NQc + q0)*Dc + h*DKc;
    const float* kbase = kh + (size_t)b*NKc*DKc;
    const float* vbase = vT + (size_t)b*DVc*NKc;
    float* abase = attn + ((size_t)(h*Bc + b)*NQc + q0)*NKc;

    // ---- Phase 1 ----
    ldconvG<64,128,SSTR>(qbase, Dc, Ahp, Alp, tid);

    const float scale = 0.08838834764831845f;
    float rm_[2] = {-1e30f, -1e30f}, rl_[2] = {0.f, 0.f};

    for (int kt = 0; kt < KTILES; kt++){
        ldconvG<128,128,SSTR>(kbase + (size_t)(kt*128)*DKc, DKc, Bhp, Blp, tid);
        __syncthreads();

        float c[8][4];
#pragma unroll
        for (int j=0;j<8;j++) for (int q=0;q<4;q++) c[j][q]=0.f;
#pragma unroll
        for (int ks = 0; ks < 8; ks++)
            wstep64<SSTR,SSTR>(Ah, Al, Bh, Bl, ks, warp_m, warp_n, lane, c);

#pragma unroll
        for (int rh = 0; rh < 2; rh++){
            int rowl = warp_m*16 + rh*8 + (lane >> 2);
            const float* mrow = mask + ((size_t)b*NQc + q0 + rowl)*NKc + kt*128;
            float* arow = abase + (size_t)rowl*NKc + kt*128;
            float sv[16];
            float mloc = -1e30f;
#pragma unroll
            for (int nt = 0; nt < 8; nt++){
                int col = warp_n*64 + nt*8 + ((lane & 3) << 1);
                float2 mv = *(const float2*)(mrow + col);
                sv[2*nt+0] = fmaf(c[nt][rh*2+0], scale, mv.x);
                sv[2*nt+1] = fmaf(c[nt][rh*2+1], scale, mv.y);
                *(float2*)(arow + col) = make_float2(sv[2*nt+0], sv[2*nt+1]);
                mloc = fmaxf(mloc, fmaxf(sv[2*nt+0], sv[2*nt+1]));
            }
#pragma unroll
            for (int off = 1; off <= 2; off <<= 1)
                mloc = fmaxf(mloc, __shfl_xor_sync(0xFFFFFFFFu, mloc, off));
            float let = 0.f;
#pragma unroll
            for (int nt = 0; nt < 8; nt++){
                let += __expf(sv[2*nt+0] - mloc);
                let += __expf(sv[2*nt+1] - mloc);
            }
#pragma unroll
            for (int off = 1; off <= 2; off <<= 1)
                let += __shfl_xor_sync(0xFFFFFFFFu, let, off);
            float nm = fmaxf(rm_[rh], mloc);
            rl_[rh] = rl_[rh]*__expf(rm_[rh] - nm) + let*__expf(mloc - nm);
            rm_[rh] = nm;
        }
        __syncthreads();
    }

    // ---- stat combine ----
#pragma unroll
    for (int rh = 0; rh < 2; rh++){
        int rowl = warp_m*16 + rh*8 + (lane >> 2);
        if ((lane & 3) == 0){
            sM2[warp_n][rowl] = rm_[rh];
            sL2[warp_n][rowl] = rl_[rh];
        }
    }
    __syncthreads();
    if (tid < 64){
        float m0 = sM2[0][tid], m1 = sM2[1][tid];
        float M = fmaxf(m0, m1);
        float L = sL2[0][tid]*__expf(m0 - M) + sL2[1][tid]*__expf(m1 - M);
        Ms[tid] = M; Li[tid] = 1.0f / L;
    }
    __syncthreads();

    // ---- Phase 2 ----
    float c[8][4];
#pragma unroll
    for (int j=0;j<8;j++) for (int q=0;q<4;q++) c[j][q]=0.f;

    for (int kt = 0; kt < KTILES; kt++){
#pragma unroll
        for (int i = 0; i < 8; i++){
            int idx = tid + i*256;
            int row = idx >> 5, c4 = (idx & 31) << 2;
            float* ap = abase + (size_t)row*NKc + kt*128 + c4;
            float4 s = *(float4*)ap;
            float mm = Ms[row], li = Li[row];
            float4 p;
            p.x = __expf(s.x - mm)*li; p.y = __expf(s.y - mm)*li;
            p.z = __expf(s.z - mm)*li; p.w = __expf(s.w - mm)*li;
            *(float4*)ap = p;
            int off = (row*SSTR + c4)*2;
            *(uint2*)(Ahp+off) = make_uint2(pkbf2(p.x,p.y), pkbf2(p.z,p.w));
            *(uint2*)(Alp+off) = make_uint2(pkbf2(bres(p.x),bres(p.y)),
                                            pkbf2(bres(p.z),bres(p.w)));
        }
        ldconvG<128,128,SSTR>(vbase + kt*128, NKc, Bhp, Blp, tid);
        __syncthreads();
#pragma unroll
        for (int ks = 0; ks < 8; ks++)
            wstep64<SSTR,SSTR>(Ah, Al, Bh, Bl, ks, warp_m, warp_n, lane, c);
        __syncthreads();
    }

#pragma unroll
    for (int rh = 0; rh < 2; rh++){
        int row = q0 + warp_m*16 + rh*8 + (lane >> 2);
        float* op = outh + (size_t)(b*NQc + row)*(Hc*DVc) + h*DVc;
#pragma unroll
        for (int nt = 0; nt < 8; nt++){
            int col = warp_n*64 + nt*8 + ((lane & 3) << 1);
            *(float2*)(op + col) = make_float2(c[nt][rh*2+0], c[nt][rh*2+1]);
        }
    }
}

// ---------------------------------------------------------------------------
extern "C" void kernel_launch(void* const* d_in, const int* in_sizes, int n_in,
                              void* d_out, int out_size)
{
    const float* q    = (const float*)d_in[0];
    const float* k    = (const float*)d_in[1];
    const float* v    = (const float*)d_in[2];
    const float* mask = (const float*)d_in[3];
    const float* Wq   = (const float*)d_in[4];
    const float* bq   = (const float*)d_in[5];
    const float* Wk   = (const float*)d_in[6];
    const float* bk   = (const float*)d_in[7];
    const float* Wv   = (const float*)d_in[8];
    const float* bv   = (const float*)d_in[9];
    const float* Wo   = (const float*)d_in[10];
    const float* bo   = (const float*)d_in[11];

    float* attn = (float*)d_out;
    float* outp = attn + (size_t)HBc*NQc*NKc;

    float *qh,*kh,*vh,*vT,*outh;
    cudaGetSymbolAddress((void**)&qh,   g_qh);
    cudaGetSymbolAddress((void**)&kh,   g_kh);
    cudaGetSymbolAddress((void**)&vh,   g_vh);
    cudaGetSymbolAddress((void**)&vT,   g_vT);
    cudaGetSymbolAddress((void**)&outh, g_outh);

    cudaFuncSetAttribute(proj_mma,   cudaFuncAttributeMaxDynamicSharedMemorySize, PROJ_SM);
    cudaFuncSetAttribute(fused_attn, cudaFuncAttributeMaxDynamicSharedMemorySize, FUS_SM);

    dim3 blk(256);
    const int Mr = Bc*NQc;   // 8192

    proj_mma<<<dim3((Hc*DKc)/128, Mr/128), blk, PROJ_SM>>>(q, Wq, bq, qh, Mr, Hc*DKc, Dc);
    proj_mma<<<dim3(1,            Mr/128), blk, PROJ_SM>>>(k, Wk, bk, kh, Mr, DKc, Dc);
    proj_mma<<<dim3(1,            Mr/128), blk, PROJ_SM>>>(v, Wv, bv, vh, Mr, DVc, Dc);

    transpose_v<<<dim3(NKc/32, DVc/32, Bc), dim3(32,8)>>>(vh, vT);

    fused_attn<<<dim3(NQc/64, HBc), blk, FUS_SM>>>(qh, kh, vT, mask, attn, outh);

    proj_mma<<<dim3(DOc/128, Mr/128), blk, PROJ_SM>>>(outh, Wo, bo, outp, Mr, DOc, Hc*DVc);
}

// round 14
// speedup vs baseline: 1.8771x; 1.1920x over previous
#include <cuda_runtime.h>
#include <cuda_bf16.h>
#include <cuda_fp16.h>
#include <math.h>
#include <stdint.h>

typedef unsigned int u32;

#define Bc   4
#define NQc  2048
#define NKc  2048
#define Dc   1024
#define Hc   8
#define DKc  128
#define DVc  128
#define DOc  1024
#define HBc  32
#define KTILES 16

__device__ float g_qh  [(size_t)Bc*NQc*Hc*DKc];
__device__ float g_kh  [(size_t)Bc*NKc*DKc];
__device__ float g_vh  [(size_t)Bc*NKc*DVc];
__device__ float g_outh[(size_t)Bc*NQc*Hc*DVc];

// ---------------- helpers ---------------------------------------------------
__device__ __forceinline__ u32 s2u(const void* p){
    u32 a; asm("{ .reg .u64 t; cvta.to.shared.u64 t, %1; cvt.u32.u64 %0, t; }"
               : "=r"(a) : "l"(p)); return a;
}
// bf16 helpers (projection path)
__device__ __forceinline__ u32 pkbf2(float a, float b){
    u32 ra = (u32)__bfloat16_as_ushort(__float2bfloat16(a));
    u32 rb = (u32)__bfloat16_as_ushort(__float2bfloat16(b));
    return ra | (rb << 16);
}
__device__ __forceinline__ float bres(float x){
    return x - __bfloat162float(__float2bfloat16(x));
}
// fp16 helpers (fused attention path)
__device__ __forceinline__ u32 pkhf2(float a, float b){
    __half2 h = __floats2half2_rn(a, b);
    return *(u32*)&h;
}
__device__ __forceinline__ float hres(float x){
    return x - __half2float(__float2half_rn(x));
}
__device__ __forceinline__ void ldmx4(u32* r, u32 addr){
    asm volatile("ldmatrix.sync.aligned.m8n8.x4.shared.b16 {%0,%1,%2,%3}, [%4];"
        : "=r"(r[0]), "=r"(r[1]), "=r"(r[2]), "=r"(r[3]) : "r"(addr));
}
__device__ __forceinline__ void mma16816(float* c, const u32* a, u32 b0, u32 b1){
    asm volatile("mma.sync.aligned.m16n8k16.row.col.f32.bf16.bf16.f32 "
        "{%0,%1,%2,%3}, {%4,%5,%6,%7}, {%8,%9}, {%0,%1,%2,%3};"
        : "+f"(c[0]), "+f"(c[1]), "+f"(c[2]), "+f"(c[3])
        : "r"(a[0]), "r"(a[1]), "r"(a[2]), "r"(a[3]), "r"(b0), "r"(b1));
}
__device__ __forceinline__ void mma16816h(float* c, const u32* a, u32 b0, u32 b1){
    asm volatile("mma.sync.aligned.m16n8k16.row.col.f32.f16.f16.f32 "
        "{%0,%1,%2,%3}, {%4,%5,%6,%7}, {%8,%9}, {%0,%1,%2,%3};"
        : "+f"(c[0]), "+f"(c[1]), "+f"(c[2]), "+f"(c[3])
        : "r"(a[0]), "r"(a[1]), "r"(a[2]), "r"(a[3]), "r"(b0), "r"(b1));
}

// rows x COLS fp32 -> bf16 hi/lo smem (projection path)
template<int ROWS, int COLS, int STRIDE>
__device__ __forceinline__ void ldconvG(const float* __restrict__ g, int ldA,
                                        char* smHi, char* smLo, int tid){
    const int PER = (ROWS*COLS/4)/256;
#pragma unroll
    for (int i = 0; i < PER; i++){
        int idx = tid + i*256;
        int row = idx / (COLS/4);
        int c4  = (idx % (COLS/4))*4;
        float4 v = *(const float4*)(g + (size_t)row*ldA + c4);
        int off = (row*STRIDE + c4)*2;
        *(uint2*)(smHi+off) = make_uint2(pkbf2(v.x,v.y), pkbf2(v.z,v.w));
        *(uint2*)(smLo+off) = make_uint2(pkbf2(bres(v.x),bres(v.y)),
                                         pkbf2(bres(v.z),bres(v.w)));
    }
}
// rows x 128 fp32 -> fp16 hi+lo smem (fused B operand)
template<int ROWS, int STRIDE>
__device__ __forceinline__ void ldconvH2(const float* __restrict__ g, int ldA,
                                         char* smHi, char* smLo, int tid){
    const int PER = (ROWS*32)/256;
#pragma unroll
    for (int i = 0; i < PER; i++){
        int idx = tid + i*256;
        int row = idx >> 5;
        int c4  = (idx & 31) << 2;
        float4 v = *(const float4*)(g + (size_t)row*ldA + c4);
        int off = (row*STRIDE + c4)*2;
        *(uint2*)(smHi+off) = make_uint2(pkhf2(v.x,v.y), pkhf2(v.z,v.w));
        *(uint2*)(smLo+off) = make_uint2(pkhf2(hres(v.x),hres(v.y)),
                                         pkhf2(hres(v.z),hres(v.w)));
    }
}
// rows x 128 fp32 -> fp16 single plane (fused A operand)
template<int ROWS, int STRIDE>
__device__ __forceinline__ void ldconvH1(const float* __restrict__ g, int ldA,
                                         char* smHi, int tid){
    const int PER = (ROWS*32)/256;
#pragma unroll
    for (int i = 0; i < PER; i++){
        int idx = tid + i*256;
        int row = idx >> 5;
        int c4  = (idx & 31) << 2;
        float4 v = *(const float4*)(g + (size_t)row*ldA + c4);
        *(uint2*)(smHi + (row*STRIDE + c4)*2) =
            make_uint2(pkhf2(v.x,v.y), pkhf2(v.z,v.w));
    }
}

// 128x128-output warp step (proj, bf16x3): warp computes 32x64
template<int SA, int SB>
__device__ __forceinline__ void wstep(u32 Ah, u32 Al, u32 Bh, u32 Bl,
                                      int ks, int warp_m, int warp_n, int lane,
                                      float c[2][8][4]){
    const int rsel = lane & 15, ksel = (lane >> 4) << 3;
    const int kb = ks*16 + ksel;
    u32 ah[2][4], al[2][4], bh[4][4], bl[4][4];
#pragma unroll
    for (int mt = 0; mt < 2; mt++){
        u32 off = (u32)((warp_m*32 + mt*16 + rsel)*SA + kb)*2;
        ldmx4(ah[mt], Ah + off);
        ldmx4(al[mt], Al + off);
    }
#pragma unroll
    for (int p = 0; p < 4; p++){
        u32 off = (u32)((warp_n*64 + p*16 + rsel)*SB + kb)*2;
        ldmx4(bh[p], Bh + off);
        ldmx4(bl[p], Bl + off);
    }
#pragma unroll
    for (int mt = 0; mt < 2; mt++)
#pragma unroll
        for (int nt = 0; nt < 8; nt++){
            int p = nt >> 1, s = nt & 1;
            mma16816(c[mt][nt], ah[mt], bh[p][s], bh[p][2+s]);
            mma16816(c[mt][nt], ah[mt], bl[p][s], bl[p][2+s]);
            mma16816(c[mt][nt], al[mt], bh[p][s], bh[p][2+s]);
        }
}

// 64x128-output warp step (fused, fp16 2-term): warp computes 16x64
template<int SA, int SB>
__device__ __forceinline__ void wstep64h(u32 Ah, u32 Bh, u32 Bl,
                                         int ks, int warp_m, int warp_n, int lane,
                                         float c[8][4]){
    const int rsel = lane & 15, ksel = (lane >> 4) << 3;
    const int kb = ks*16 + ksel;
    u32 ah[4], bh[4][4], bl[4][4];
    ldmx4(ah, Ah + (u32)((warp_m*16 + rsel)*SA + kb)*2);
#pragma unroll
    for (int p = 0; p < 4; p++){
        u32 off = (u32)((warp_n*64 + p*16 + rsel)*SB + kb)*2;
        ldmx4(bh[p], Bh + off);
        ldmx4(bl[p], Bl + off);
    }
#pragma unroll
    for (int nt = 0; nt < 8; nt++){
        int p = nt >> 1, s = nt & 1;
        mma16816h(c[nt], ah, bh[p][s], bh[p][2+s]);
        mma16816h(c[nt], ah, bl[p][s], bl[p][2+s]);
    }
}

// ---------------------------------------------------------------------------
// proj: C[M,N] = A[M,K] @ W[N,K]^T + bias (bf16x3, 2 CTAs/SM, unchanged).
// ---------------------------------------------------------------------------
#define PSTR 72
#define PTILE (128*PSTR*2)
#define PROJ_SM (4*PTILE)    // 73728 per CTA -> 2 CTAs/SM
__device__ __forceinline__ void proj_body(
    const float* __restrict__ A, const float* __restrict__ W,
    const float* __restrict__ bias, float* __restrict__ C,
    int M, int N, int K, int m0, int n0, char* sm)
{
    u32 sb = s2u(sm);
    const int tid = threadIdx.x, lane = tid & 31, wid = tid >> 5;
    const int warp_m = wid & 3, warp_n = wid >> 2;

    char* Ahp = sm;            char* Alp = sm + PTILE;
    char* Bhp = sm + 2*PTILE;  char* Blp = sm + 3*PTILE;
    const u32 Ah = sb, Al = sb + PTILE, Bh = sb + 2*PTILE, Bl = sb + 3*PTILE;

    float c[2][8][4];
#pragma unroll
    for (int i=0;i<2;i++) for (int j=0;j<8;j++) for (int q=0;q<4;q++) c[i][j][q]=0.f;

    const int NC = K/64;
    for (int kc = 0; kc < NC; kc++){
        ldconvG<128,64,PSTR>(A + (size_t)m0*K + kc*64, K, Ahp, Alp, tid);
        ldconvG<128,64,PSTR>(W + (size_t)n0*K + kc*64, K, Bhp, Blp, tid);
        __syncthreads();
#pragma unroll
        for (int ks = 0; ks < 4; ks++)
            wstep<PSTR,PSTR>(Ah, Al, Bh, Bl, ks, warp_m, warp_n, lane, c);
        __syncthreads();
    }

#pragma unroll
    for (int mt = 0; mt < 2; mt++)
#pragma unroll
        for (int rh = 0; rh < 2; rh++){
            int row = m0 + warp_m*32 + mt*16 + rh*8 + (lane >> 2);
#pragma unroll
            for (int nt = 0; nt < 8; nt++){
                int col = n0 + warp_n*64 + nt*8 + ((lane & 3) << 1);
                float2 o;
                o.x = c[mt][nt][rh*2+0] + __ldg(bias + col);
                o.y = c[mt][nt][rh*2+1] + __ldg(bias + col + 1);
                *(float2*)(C + (size_t)row*N + col) = o;
            }
        }
}

__global__ void __launch_bounds__(256,2) proj_mma(
    const float* __restrict__ A, const float* __restrict__ W,
    const float* __restrict__ bias, float* __restrict__ C,
    int M, int N, int K)
{
    extern __shared__ char sm[];
    proj_body(A, W, bias, C, M, N, K, blockIdx.y << 7, blockIdx.x << 7, sm);
}

// merged K+V projection: blockIdx.x selects which weight/output pair
__global__ void __launch_bounds__(256,2) proj_mma_kv(
    const float* __restrict__ kin, const float* __restrict__ vin,
    const float* __restrict__ Wk, const float* __restrict__ bk, float* __restrict__ kh,
    const float* __restrict__ Wv, const float* __restrict__ bv, float* __restrict__ vh,
    int M, int K)
{
    extern __shared__ char sm[];
    if (blockIdx.x == 0)
        proj_body(kin, Wk, bk, kh, M, DKc, K, blockIdx.y << 7, 0, sm);
    else
        proj_body(vin, Wv, bv, vh, M, DVc, K, blockIdx.y << 7, 0, sm);
}

// vh [b,k,d] -> vT [b,d,k]
__device__ float g_vT[(size_t)Bc*DVc*NKc];
__global__ void transpose_v(const float* __restrict__ vh, float* __restrict__ vT){
    __shared__ float t[32][33];
    int b = blockIdx.z;
    int k0 = blockIdx.x*32, d0 = blockIdx.y*32;
    int x = threadIdx.x, y = threadIdx.y;
#pragma unroll
    for (int i = 0; i < 32; i += 8)
        t[y+i][x] = vh[(size_t)(b*NKc + k0 + y + i)*DVc + d0 + x];
    __syncthreads();
#pragma unroll
    for (int i = 0; i < 32; i += 8)
        vT[((size_t)b*DVc + d0 + y + i)*NKc + k0 + x] = t[x][y+i];
}

// ---------------------------------------------------------------------------
// fused attention, fp16 2-term split (A single plane, B hi+lo), 2 CTAs/SM.
// ---------------------------------------------------------------------------
#define SSTR 136
#define QTILE (64*SSTR*2)    // 17408 (1 plane, fp16)
#define KTILE (128*SSTR*2)   // 34816 per plane
#define FUS_SM (QTILE + 2*KTILE)  // 87040
__global__ void __launch_bounds__(256,2) fused_attn(
    const float* __restrict__ qh, const float* __restrict__ kh,
    const float* __restrict__ vT, const float* __restrict__ mask,
    float* __restrict__ attn, float* __restrict__ outh)
{
    extern __shared__ char sm[];
    __shared__ float Ms[64], Li[64];
    __shared__ float sM2[2][64], sL2[2][64];
    u32 sb = s2u(sm);
    const int tid = threadIdx.x, lane = tid & 31, wid = tid >> 5;
    const int warp_m = wid & 3, warp_n = wid >> 2;
    const int q0 = blockIdx.x << 6;
    const int hb = blockIdx.y, b = hb >> 3, h = hb & 7;

    char* Ahp = sm;                 // Q, later P (fp16 single plane)
    char* Bhp = sm + QTILE;         // K/V hi
    char* Blp = sm + QTILE + KTILE; // K/V lo
    const u32 Ah = sb, Bh = sb + QTILE, Bl = sb + QTILE + KTILE;

    const float* qbase = qh + (size_t)(b*NQc + q0)*Dc + h*DKc;
    const float* kbase = kh + (size_t)b*NKc*DKc;
    const float* vbase = vT + (size_t)b*DVc*NKc;
    float* abase = attn + ((size_t)(h*Bc + b)*NQc + q0)*NKc;

    // ---- Phase 1 ----
    ldconvH1<64,SSTR>(qbase, Dc, Ahp, tid);

    const float scale = 0.08838834764831845f;
    float rm_[2] = {-1e30f, -1e30f}, rl_[2] = {0.f, 0.f};

    for (int kt = 0; kt < KTILES; kt++){
        ldconvH2<128,SSTR>(kbase + (size_t)(kt*128)*DKc, DKc, Bhp, Blp, tid);
        __syncthreads();

        float c[8][4];
#pragma unroll
        for (int j=0;j<8;j++) for (int q=0;q<4;q++) c[j][q]=0.f;
#pragma unroll
        for (int ks = 0; ks < 8; ks++)
            wstep64h<SSTR,SSTR>(Ah, Bh, Bl, ks, warp_m, warp_n, lane, c);

#pragma unroll
        for (int rh = 0; rh < 2; rh++){
            int rowl = warp_m*16 + rh*8 + (lane >> 2);
            const float* mrow = mask + ((size_t)b*NQc + q0 + rowl)*NKc + kt*128;
            float* arow = abase + (size_t)rowl*NKc + kt*128;
            float sv[16];
            float mloc = -1e30f;
#pragma unroll
            for (int nt = 0; nt < 8; nt++){
                int col = warp_n*64 + nt*8 + ((lane & 3) << 1);
                float2 mv = *(const float2*)(mrow + col);
                sv[2*nt+0] = fmaf(c[nt][rh*2+0], scale, mv.x);
                sv[2*nt+1] = fmaf(c[nt][rh*2+1], scale, mv.y);
                *(float2*)(arow + col) = make_float2(sv[2*nt+0], sv[2*nt+1]);
                mloc = fmaxf(mloc, fmaxf(sv[2*nt+0], sv[2*nt+1]));
            }
#pragma unroll
            for (int off = 1; off <= 2; off <<= 1)
                mloc = fmaxf(mloc, __shfl_xor_sync(0xFFFFFFFFu, mloc, off));
            float let = 0.f;
#pragma unroll
            for (int nt = 0; nt < 8; nt++){
                let += __expf(sv[2*nt+0] - mloc);
                let += __expf(sv[2*nt+1] - mloc);
            }
#pragma unroll
            for (int off = 1; off <= 2; off <<= 1)
                let += __shfl_xor_sync(0xFFFFFFFFu, let, off);
            float nm = fmaxf(rm_[rh], mloc);
            rl_[rh] = rl_[rh]*__expf(rm_[rh] - nm) + let*__expf(mloc - nm);
            rm_[rh] = nm;
        }
        __syncthreads();
    }

    // ---- stat combine ----
#pragma unroll
    for (int rh = 0; rh < 2; rh++){
        int rowl = warp_m*16 + rh*8 + (lane >> 2);
        if ((lane & 3) == 0){
            sM2[warp_n][rowl] = rm_[rh];
            sL2[warp_n][rowl] = rl_[rh];
        }
    }
    __syncthreads();
    if (tid < 64){
        float m0 = sM2[0][tid], m1 = sM2[1][tid];
        float M = fmaxf(m0, m1);
        float L = sL2[0][tid]*__expf(m0 - M) + sL2[1][tid]*__expf(m1 - M);
        Ms[tid] = M; Li[tid] = 1.0f / L;
    }
    __syncthreads();

    // ---- Phase 2: P = exp(s - M)*Li; P fp16 single plane; V hi+lo ----
    float c[8][4];
#pragma unroll
    for (int j=0;j<8;j++) for (int q=0;q<4;q++) c[j][q]=0.f;

    for (int kt = 0; kt < KTILES; kt++){
#pragma unroll
        for (int i = 0; i < 8; i++){
            int idx = tid + i*256;
            int row = idx >> 5, c4 = (idx & 31) << 2;
            float* ap = abase + (size_t)row*NKc + kt*128 + c4;
            float4 s = *(float4*)ap;
            float mm = Ms[row], li = Li[row];
            float4 p;
            p.x = __expf(s.x - mm)*li; p.y = __expf(s.y - mm)*li;
            p.z = __expf(s.z - mm)*li; p.w = __expf(s.w - mm)*li;
            *(float4*)ap = p;
            *(uint2*)(Ahp + (row*SSTR + c4)*2) =
                make_uint2(pkhf2(p.x,p.y), pkhf2(p.z,p.w));
        }
        ldconvH2<128,SSTR>(vbase + kt*128, NKc, Bhp, Blp, tid);
        __syncthreads();
#pragma unroll
        for (int ks = 0; ks < 8; ks++)
            wstep64h<SSTR,SSTR>(Ah, Bh, Bl, ks, warp_m, warp_n, lane, c);
        __syncthreads();
    }

#pragma unroll
    for (int rh = 0; rh < 2; rh++){
        int row = q0 + warp_m*16 + rh*8 + (lane >> 2);
        float* op = outh + (size_t)(b*NQc + row)*(Hc*DVc) + h*DVc;
#pragma unroll
        for (int nt = 0; nt < 8; nt++){
            int col = warp_n*64 + nt*8 + ((lane & 3) << 1);
            *(float2*)(op + col) = make_float2(c[nt][rh*2+0], c[nt][rh*2+1]);
        }
    }
}

// ---------------------------------------------------------------------------
extern "C" void kernel_launch(void* const* d_in, const int* in_sizes, int n_in,
                              void* d_out, int out_size)
{
    const float* q    = (const float*)d_in[0];
    const float* k    = (const float*)d_in[1];
    const float* v    = (const float*)d_in[2];
    const float* mask = (const float*)d_in[3];
    const float* Wq   = (const float*)d_in[4];
    const float* bq   = (const float*)d_in[5];
    const float* Wk   = (const float*)d_in[6];
    const float* bk   = (const float*)d_in[7];
    const float* Wv   = (const float*)d_in[8];
    const float* bv   = (const float*)d_in[9];
    const float* Wo   = (const float*)d_in[10];
    const float* bo   = (const float*)d_in[11];

    float* attn = (float*)d_out;
    float* outp = attn + (size_t)HBc*NQc*NKc;

    float *qh,*kh,*vh,*vT,*outh;
    cudaGetSymbolAddress((void**)&qh,   g_qh);
    cudaGetSymbolAddress((void**)&kh,   g_kh);
    cudaGetSymbolAddress((void**)&vh,   g_vh);
    cudaGetSymbolAddress((void**)&vT,   g_vT);
    cudaGetSymbolAddress((void**)&outh, g_outh);

    cudaFuncSetAttribute(proj_mma,    cudaFuncAttributeMaxDynamicSharedMemorySize, PROJ_SM);
    cudaFuncSetAttribute(proj_mma_kv, cudaFuncAttributeMaxDynamicSharedMemorySize, PROJ_SM);
    cudaFuncSetAttribute(fused_attn,  cudaFuncAttributeMaxDynamicSharedMemorySize, FUS_SM);

    dim3 blk(256);
    const int Mr = Bc*NQc;   // 8192

    proj_mma<<<dim3((Hc*DKc)/128, Mr/128), blk, PROJ_SM>>>(q, Wq, bq, qh, Mr, Hc*DKc, Dc);
    proj_mma_kv<<<dim3(2, Mr/128), blk, PROJ_SM>>>(k, v, Wk, bk, kh, Wv, bv, vh, Mr, Dc);

    transpose_v<<<dim3(NKc/32, DVc/32, Bc), dim3(32,8)>>>(vh, vT);

    fused_attn<<<dim3(NQc/64, HBc), blk, FUS_SM>>>(qh, kh, vT, mask, attn, outh);

    proj_mma<<<dim3(DOc/128, Mr/128), blk, PROJ_SM>>>(outh, Wo, bo, outp, Mr, DOc, Hc*DVc);
}